// round 3
// baseline (speedup 1.0000x reference)
#include <cuda_runtime.h>
#include <mma.h>
#include <cstdint>

using namespace nvcuda;

#define NMAX 100000
#define EMAX 1600000
#define HID 128

// ---------------- scratch (device globals; no allocations allowed) ----------
__device__ float g_event_feat[(size_t)NMAX * HID];
__device__ float g_xg[(size_t)NMAX * HID];
__device__ float g_diffused[(size_t)NMAX * HID];
__device__ float g_corrected[(size_t)NMAX * HID];
__device__ int   g_deg[NMAX];
__device__ float g_dis[NMAX];
__device__ int   g_rowstart[NMAX];
__device__ int   g_cursor[NMAX];
__device__ int   g_csr[EMAX];
__device__ int   g_bsum[1024];
__device__ int   g_is64;

enum { EPI_RELU = 0, EPI_NONE = 1, EPI_GATE = 2 };

// ---------------- wmma tf32 GEMM ----------------------------------------------
// C[M,128] = epi( concat(A0[:,0:K0], A1[:,K0:KTOT]) @ W[KTOT,128] + bias )
// W is the natural [K][128] row-major weight (== wmma matrix_b row_major).
// Block: 256 thr = 8 warps; tile 128M x 128N; warp = 32M x 64N; BK = 32.
template<int KTOT, int K0, int EPI>
__global__ void __launch_bounds__(256, 4)
gemm_wmma(const float* __restrict__ A0, const float* __restrict__ A1,
          const float* __restrict__ W,  const float* __restrict__ bias,
          const float* __restrict__ E0, const float* __restrict__ E1,
          float* __restrict__ C, int M)
{
    constexpr int BK   = 32;
    constexpr int NCH  = KTOT / BK;
    constexpr int LDA  = BK + 8;    // 40
    constexpr int LDB  = HID + 8;   // 136
    constexpr int LDC  = 72;        // half-tile C: 128 x 64, ld 72

    // union buffer: mainloop (As+Bs) then epilogue (Cs)
    constexpr int SZ_AB = 128 * LDA + BK * LDB;   // 9472 floats
    constexpr int SZ_C  = 128 * LDC;              // 9216 floats
    __shared__ __align__(16) float smem_buf[SZ_AB > SZ_C ? SZ_AB : SZ_C];
    __shared__ float s_bias[HID];

    float* As = smem_buf;
    float* Bs = smem_buf + 128 * LDA;
    float* Cs = smem_buf;

    const int tid   = threadIdx.x;
    const int wid   = tid >> 5;
    const int warpM = wid & 3;       // 4 warps along M
    const int warpN = wid >> 2;      // 2 warps along N
    const int m0    = blockIdx.x * 128;

    if (EPI != EPI_NONE && tid < HID) s_bias[tid] = bias[tid];

    wmma::fragment<wmma::accumulator, 16, 16, 8, float> c[2][4];
#pragma unroll
    for (int mi = 0; mi < 2; mi++)
#pragma unroll
        for (int ni = 0; ni < 4; ni++) wmma::fill_fragment(c[mi][ni], 0.f);

    for (int ch = 0; ch < NCH; ch++) {
        const int kc = ch * BK;
        // A source select (concat along K)
        const float* Ap; int stride, kc2;
        if (KTOT == K0 || kc < K0) { Ap = A0; stride = K0;        kc2 = kc; }
        else                       { Ap = A1; stride = KTOT - K0; kc2 = kc - K0; }
        // load A tile [128 x 32]: 1024 float4, 4 per thread
#pragma unroll
        for (int i = 0; i < 4; i++) {
            const int idx = tid + i * 256;
            const int r = idx >> 3, q = idx & 7;
            int gr = m0 + r; if (gr > M - 1) gr = M - 1;
            const float4 v = *(const float4*)(Ap + (size_t)gr * stride + kc2 + q * 4);
            *(float4*)(As + r * LDA + q * 4) = v;
        }
        // load B tile [32 x 128]: 1024 float4, 4 per thread
#pragma unroll
        for (int i = 0; i < 4; i++) {
            const int idx = tid + i * 256;
            const int r = idx >> 5, q = idx & 31;
            const float4 v = *(const float4*)(W + (size_t)(kc + r) * HID + q * 4);
            *(float4*)(Bs + r * LDB + q * 4) = v;
        }
        __syncthreads();

#pragma unroll
        for (int ks = 0; ks < BK / 8; ks++) {
            wmma::fragment<wmma::matrix_a, 16, 16, 8, wmma::precision::tf32, wmma::row_major> a[2];
            wmma::fragment<wmma::matrix_b, 16, 16, 8, wmma::precision::tf32, wmma::row_major> b[4];
#pragma unroll
            for (int mi = 0; mi < 2; mi++) {
                wmma::load_matrix_sync(a[mi], As + (warpM * 32 + mi * 16) * LDA + ks * 8, LDA);
#pragma unroll
                for (int t = 0; t < a[mi].num_elements; t++)
                    a[mi].x[t] = wmma::__float_to_tf32(a[mi].x[t]);
            }
#pragma unroll
            for (int ni = 0; ni < 4; ni++) {
                wmma::load_matrix_sync(b[ni], Bs + (ks * 8) * LDB + warpN * 64 + ni * 16, LDB);
#pragma unroll
                for (int t = 0; t < b[ni].num_elements; t++)
                    b[ni].x[t] = wmma::__float_to_tf32(b[ni].x[t]);
            }
#pragma unroll
            for (int mi = 0; mi < 2; mi++)
#pragma unroll
                for (int ni = 0; ni < 4; ni++)
                    wmma::mma_sync(c[mi][ni], a[mi], b[ni], c[mi][ni]);
        }
        __syncthreads();
    }

    // ---------------- epilogue: two 128x64 column halves via smem -------------
#pragma unroll
    for (int h = 0; h < 2; h++) {
        if (warpN == h) {
#pragma unroll
            for (int mi = 0; mi < 2; mi++)
#pragma unroll
                for (int ni = 0; ni < 4; ni++)
                    wmma::store_matrix_sync(Cs + (warpM * 32 + mi * 16) * LDC + ni * 16,
                                            c[mi][ni], LDC, wmma::mem_row_major);
        }
        __syncthreads();
        // 128 rows x 64 cols = 2048 float4, 8 per thread
#pragma unroll
        for (int i = 0; i < 8; i++) {
            const int idx = tid + i * 256;
            const int row = idx >> 4, c4 = (idx & 15) * 4;
            const int grow = m0 + row;
            if (grow >= M) continue;
            const int gcol = h * 64 + c4;
            float v[4];
#pragma unroll
            for (int j = 0; j < 4; j++) v[j] = Cs[row * LDC + c4 + j];
            float4 o;
            if (EPI == EPI_NONE) {
                o = make_float4(v[0], v[1], v[2], v[3]);
            } else if (EPI == EPI_RELU) {
                o.x = fmaxf(v[0] + s_bias[gcol + 0], 0.f);
                o.y = fmaxf(v[1] + s_bias[gcol + 1], 0.f);
                o.z = fmaxf(v[2] + s_bias[gcol + 2], 0.f);
                o.w = fmaxf(v[3] + s_bias[gcol + 3], 0.f);
            } else { // EPI_GATE
                float4 a0 = *(const float4*)(E0 + (size_t)grow * HID + gcol);
                float4 a1 = *(const float4*)(E1 + (size_t)grow * HID + gcol);
                float g0 = 1.f / (1.f + __expf(-(v[0] + s_bias[gcol + 0])));
                float g1 = 1.f / (1.f + __expf(-(v[1] + s_bias[gcol + 1])));
                float g2 = 1.f / (1.f + __expf(-(v[2] + s_bias[gcol + 2])));
                float g3 = 1.f / (1.f + __expf(-(v[3] + s_bias[gcol + 3])));
                o.x = fmaf(a1.x - a0.x, g0, a0.x);
                o.y = fmaf(a1.y - a0.y, g1, a0.y);
                o.z = fmaf(a1.z - a0.z, g2, a0.z);
                o.w = fmaf(a1.w - a0.w, g3, a0.w);
            }
            *(float4*)(C + (size_t)grow * HID + gcol) = o;
        }
        if (h == 0) __syncthreads();
    }
}

// ---------------- edge-index dtype sniff --------------------------------------
__global__ void detect_idx(const unsigned int* __restrict__ p, int E2) {
    __shared__ int any;
    if (threadIdx.x == 0) any = 0;
    __syncthreads();
    int nsamp = E2 / 2; if (nsamp > 2048) nsamp = 2048;
    for (int i = threadIdx.x; i < nsamp; i += blockDim.x)
        if (p[2 * i + 1] != 0u) atomicOr(&any, 1);
    __syncthreads();
    if (threadIdx.x == 0) g_is64 = any ? 0 : 1;
}

__device__ __forceinline__ int edge_val(const void* ei, size_t idx) {
    return g_is64 ? (int)((const long long*)ei)[idx] : ((const int*)ei)[idx];
}

// ---------------- degree / CSR -------------------------------------------------
__global__ void count_deg(const void* __restrict__ ei, int E) {
    int e = blockIdx.x * blockDim.x + threadIdx.x;
    if (e >= E) return;
    int d = edge_val(ei, (size_t)E + e);
    atomicAdd(&g_deg[d], 1);
}
__global__ void compute_dis(int n) {
    int i = blockIdx.x * blockDim.x + threadIdx.x;
    if (i < n) g_dis[i] = rsqrtf((float)(g_deg[i] + 1));
}
__global__ void scan1(int n) {
    __shared__ int sh[512];
    int i = blockIdx.x * 512 + threadIdx.x;
    sh[threadIdx.x] = (i < n) ? g_deg[i] : 0;
    __syncthreads();
    for (int off = 256; off > 0; off >>= 1) {
        if (threadIdx.x < off) sh[threadIdx.x] += sh[threadIdx.x + off];
        __syncthreads();
    }
    if (threadIdx.x == 0) g_bsum[blockIdx.x] = sh[0];
}
__global__ void scan2(int nb) {
    __shared__ int sh[1024];
    int tid = threadIdx.x;
    int v = (tid < nb) ? g_bsum[tid] : 0;
    sh[tid] = v;
    __syncthreads();
    for (int off = 1; off < 1024; off <<= 1) {
        int t = (tid >= off) ? sh[tid - off] : 0;
        __syncthreads();
        sh[tid] += t;
        __syncthreads();
    }
    if (tid < nb) g_bsum[tid] = sh[tid] - v;
}
__global__ void scan3(int n) {
    __shared__ int sh[512];
    int tid = threadIdx.x;
    int i = blockIdx.x * 512 + tid;
    int v = (i < n) ? g_deg[i] : 0;
    sh[tid] = v;
    __syncthreads();
    for (int off = 1; off < 512; off <<= 1) {
        int t = (tid >= off) ? sh[tid - off] : 0;
        __syncthreads();
        sh[tid] += t;
        __syncthreads();
    }
    if (i < n) {
        int rs = g_bsum[blockIdx.x] + sh[tid] - v;
        g_rowstart[i] = rs;
        g_cursor[i]   = rs;
    }
}
__global__ void fill_csr(const void* __restrict__ ei, int E) {
    int e = blockIdx.x * blockDim.x + threadIdx.x;
    if (e >= E) return;
    int s = edge_val(ei, e);
    int d = edge_val(ei, (size_t)E + e);
    int pos = atomicAdd(&g_cursor[d], 1);
    g_csr[pos] = s;
}

// ---------------- aggregation: warp per node, gather-sum -----------------------
__global__ void aggregate(const float* __restrict__ b_gcn, int n) {
    int gw   = (blockIdx.x * blockDim.x + threadIdx.x) >> 5;
    int lane = threadIdx.x & 31;
    if (gw >= n) return;
    const int node = gw;
    const float4* __restrict__ xg4 = (const float4*)g_xg;

    float4 selfv = xg4[(size_t)node * 32 + lane];
    float  dn    = g_dis[node];
    int    s0    = g_rowstart[node];
    int    cnt   = g_deg[node];

    float4 acc = make_float4(0.f, 0.f, 0.f, 0.f);
    int e = s0, eend = s0 + cnt;
    for (; e + 1 < eend; e += 2) {
        int s1 = g_csr[e], s2 = g_csr[e + 1];
        float w1 = g_dis[s1], w2 = g_dis[s2];
        float4 v1 = xg4[(size_t)s1 * 32 + lane];
        float4 v2 = xg4[(size_t)s2 * 32 + lane];
        acc.x += v1.x * w1 + v2.x * w2;
        acc.y += v1.y * w1 + v2.y * w2;
        acc.z += v1.z * w1 + v2.z * w2;
        acc.w += v1.w * w1 + v2.w * w2;
    }
    if (e < eend) {
        int s1 = g_csr[e];
        float w1 = g_dis[s1];
        float4 v1 = xg4[(size_t)s1 * 32 + lane];
        acc.x += v1.x * w1; acc.y += v1.y * w1;
        acc.z += v1.z * w1; acc.w += v1.w * w1;
    }
    const float sw = dn * dn;
    float4 b = ((const float4*)b_gcn)[lane];
    float4 o;
    o.x = fmaxf(acc.x * dn + selfv.x * sw + b.x, 0.f);
    o.y = fmaxf(acc.y * dn + selfv.y * sw + b.y, 0.f);
    o.z = fmaxf(acc.z * dn + selfv.z * sw + b.z, 0.f);
    o.w = fmaxf(acc.w * dn + selfv.w * sw + b.w, 0.f);
    ((float4*)g_diffused)[(size_t)node * 32 + lane] = o;
}

// ---------------- launcher ------------------------------------------------------
extern "C" void kernel_launch(void* const* d_in, const int* in_sizes, int n_in,
                              void* d_out, int out_size)
{
    const float* base   = (const float*)d_in[0];
    const float* ev     = (const float*)d_in[1];
    const void*  ei     = d_in[2];
    const float* W_proj = (const float*)d_in[3];
    const float* b_proj = (const float*)d_in[4];
    const float* W_gcn  = (const float*)d_in[5];
    const float* b_gcn  = (const float*)d_in[6];
    const float* W_gate = (const float*)d_in[7];
    const float* b_gate = (const float*)d_in[8];
    const float* W_fuse = (const float*)d_in[9];
    const float* b_fuse = (const float*)d_in[10];

    const int N = in_sizes[0] / HID;
    const int E = in_sizes[2] / 2;

    float *p_ef, *p_xg, *p_diff, *p_corr;
    int *p_deg;
    cudaGetSymbolAddress((void**)&p_ef,   g_event_feat);
    cudaGetSymbolAddress((void**)&p_xg,   g_xg);
    cudaGetSymbolAddress((void**)&p_diff, g_diffused);
    cudaGetSymbolAddress((void**)&p_corr, g_corrected);
    cudaGetSymbolAddress((void**)&p_deg,  g_deg);

    const int gT = (N + 127) / 128;
    const int gN = (N + 255) / 256;
    const int gE = (E + 255) / 256;
    const int nb = (N + 511) / 512;

    // edge dtype sniff + CSR prep
    detect_idx<<<1, 256>>>((const unsigned int*)ei, 2 * E);
    cudaMemsetAsync(p_deg, 0, (size_t)N * sizeof(int));

    // event_feat = relu(ev @ W_proj + b_proj)
    gemm_wmma<64, 64, EPI_RELU><<<gT, 256>>>(ev, nullptr, W_proj, b_proj,
                                             nullptr, nullptr, p_ef, N);
    // xg = event_feat @ W_gcn
    gemm_wmma<128, 128, EPI_NONE><<<gT, 256>>>(p_ef, nullptr, W_gcn, nullptr,
                                               nullptr, nullptr, p_xg, N);

    // CSR build
    count_deg<<<gE, 256>>>(ei, E);
    compute_dis<<<gN, 256>>>(N);
    scan1<<<nb, 512>>>(N);
    scan2<<<1, 1024>>>(nb);
    scan3<<<nb, 512>>>(N);
    fill_csr<<<gE, 256>>>(ei, E);

    // diffused = relu(A_norm @ xg + b_gcn)
    aggregate<<<(N * 32 + 255) / 256, 256>>>(b_gcn, N);

    // corrected = base*(1-g) + diffused*g,  g = sigmoid([base,diffused]@W_gate+b)
    gemm_wmma<256, 128, EPI_GATE><<<gT, 256>>>(base, p_diff, W_gate, b_gate,
                                               base, p_diff, p_corr, N);
    // out = relu([base, corrected] @ W_fuse + b_fuse)
    gemm_wmma<256, 128, EPI_RELU><<<gT, 256>>>(base, p_corr, W_fuse, b_fuse,
                                               nullptr, nullptr, (float*)d_out, N);
}

// round 4
// speedup vs baseline: 3.4132x; 3.4132x over previous
#include <cuda_runtime.h>
#include <cstdint>

#define NMAX 100000
#define EMAX 1600000
#define HID 128

// ---------------- scratch (device globals; no allocations allowed) ----------
__device__ float g_event_feat[(size_t)NMAX * HID];
__device__ float g_xg[(size_t)NMAX * HID];
__device__ float g_diffused[(size_t)NMAX * HID];
__device__ float g_corrected[(size_t)NMAX * HID];
__device__ int   g_deg[NMAX];
__device__ float g_dis[NMAX];
__device__ int   g_rowstart[NMAX];
__device__ int   g_cursor[NMAX];
__device__ int   g_csr[EMAX];
__device__ int   g_bsum[1024];
__device__ int   g_is64;

enum { EPI_RELU = 0, EPI_NONE = 1, EPI_GATE = 2 };

// ---------------- PTX helpers --------------------------------------------------
__device__ __forceinline__ uint32_t smem_u32(const void* p) {
    uint32_t a;
    asm("{ .reg .u64 t; cvta.to.shared.u64 t, %1; cvt.u32.u64 %0, t; }" : "=r"(a) : "l"(p));
    return a;
}
__device__ __forceinline__ void cp16(uint32_t dst, const void* src) {
    asm volatile("cp.async.cg.shared.global [%0], [%1], 16;" :: "r"(dst), "l"(src));
}
__device__ __forceinline__ void cp_commit() {
    asm volatile("cp.async.commit_group;" ::: "memory");
}
template<int N>
__device__ __forceinline__ void cp_wait() {
    asm volatile("cp.async.wait_group %0;" :: "n"(N) : "memory");
}
__device__ __forceinline__ uint32_t to_tf32(float f) {
    uint32_t u;
    asm("cvt.rna.tf32.f32 %0, %1;" : "=r"(u) : "f"(f));
    return u;
}
__device__ __forceinline__ void mma_tf32(float* c, const uint32_t* a, uint32_t b0, uint32_t b1) {
    asm volatile(
        "mma.sync.aligned.m16n8k8.row.col.f32.tf32.tf32.f32 "
        "{%0,%1,%2,%3}, {%4,%5,%6,%7}, {%8,%9}, {%0,%1,%2,%3};"
        : "+f"(c[0]), "+f"(c[1]), "+f"(c[2]), "+f"(c[3])
        : "r"(a[0]), "r"(a[1]), "r"(a[2]), "r"(a[3]), "r"(b0), "r"(b1));
}

// ---------------- mma.sync tf32 GEMM --------------------------------------------
// C[M,128] = epi( concat(A0[:,0:K0], A1[:,K0:KTOT]) @ W[KTOT,128] + bias )
// 256 thr = 8 warps; block tile 128M x 128N; warp tile 32M x 64N; BK=16, 2-stage cp.async.
template<int KTOT, int K0, int EPI>
__global__ void __launch_bounds__(256, 2)
gemm_mma(const float* __restrict__ A0, const float* __restrict__ A1,
         const float* __restrict__ W,  const float* __restrict__ bias,
         const float* __restrict__ E0, const float* __restrict__ E1,
         float* __restrict__ C, int M)
{
    constexpr int BK  = 16;
    constexpr int NCH = KTOT / BK;
    constexpr int LDA = 20;    // floats; bank-conflict-free for A-frag loads
    constexpr int LDB = 136;   // floats; bank-conflict-free for B-frag loads

    __shared__ __align__(16) float As[2][128 * LDA];  // 2 x 10240 B
    __shared__ __align__(16) float Bs[2][BK * LDB];   // 2 x  8704 B
    __shared__ float s_bias[HID];

    const int tid   = threadIdx.x;
    const int wid   = tid >> 5;
    const int lane  = tid & 31;
    const int warpM = wid & 3;
    const int warpN = wid >> 2;
    const int lr    = lane >> 2;   // 0..7
    const int lc    = lane & 3;    // 0..3
    const int m0    = blockIdx.x * 128;

    if (EPI != EPI_NONE && tid < HID) s_bias[tid] = bias[tid];

    const uint32_t as_u[2] = { smem_u32(&As[0][0]), smem_u32(&As[1][0]) };
    const uint32_t bs_u[2] = { smem_u32(&Bs[0][0]), smem_u32(&Bs[1][0]) };

    float c[2][8][4];
#pragma unroll
    for (int mi = 0; mi < 2; mi++)
#pragma unroll
        for (int ni = 0; ni < 8; ni++)
#pragma unroll
            for (int j = 0; j < 4; j++) c[mi][ni][j] = 0.f;

    // ---- async copy of one K-chunk into stage s
    auto issue = [&](int s, int ch) {
        const int kc = ch * BK;
        const float* Ap; int stride, kc2;
        if (KTOT == K0 || kc < K0) { Ap = A0; stride = K0;        kc2 = kc; }
        else                       { Ap = A1; stride = KTOT - K0; kc2 = kc - K0; }
        // A: 128 rows x 16 floats = 512 x 16B
#pragma unroll
        for (int i = 0; i < 2; i++) {
            const int idx = tid + i * 256;
            const int r = idx >> 2, q = idx & 3;
            int gr = m0 + r; if (gr > M - 1) gr = M - 1;
            cp16(as_u[s] + (uint32_t)(r * LDA + q * 4) * 4,
                 Ap + (size_t)gr * stride + kc2 + q * 4);
        }
        // B: 16 rows x 128 floats = 512 x 16B
#pragma unroll
        for (int i = 0; i < 2; i++) {
            const int idx = tid + i * 256;
            const int r = idx >> 5, q = idx & 31;
            cp16(bs_u[s] + (uint32_t)(r * LDB + q * 4) * 4,
                 W + (size_t)(kc + r) * HID + q * 4);
        }
        cp_commit();
    };

    issue(0, 0);

    for (int ch = 0; ch < NCH; ch++) {
        const int s = ch & 1;
        if (ch + 1 < NCH) { issue(s ^ 1, ch + 1); cp_wait<1>(); }
        else              { cp_wait<0>(); }
        __syncthreads();

#pragma unroll
        for (int ks = 0; ks < 2; ks++) {
            const int k = ks * 8 + lc;
            uint32_t a[2][4];
#pragma unroll
            for (int mi = 0; mi < 2; mi++) {
                const int row = warpM * 32 + mi * 16 + lr;
                a[mi][0] = to_tf32(As[s][row * LDA + k]);
                a[mi][1] = to_tf32(As[s][(row + 8) * LDA + k]);
                a[mi][2] = to_tf32(As[s][row * LDA + k + 4]);
                a[mi][3] = to_tf32(As[s][(row + 8) * LDA + k + 4]);
            }
#pragma unroll
            for (int ni = 0; ni < 8; ni++) {
                const int n = warpN * 64 + ni * 8 + lr;
                const uint32_t b0 = to_tf32(Bs[s][k * LDB + n]);
                const uint32_t b1 = to_tf32(Bs[s][(k + 4) * LDB + n]);
#pragma unroll
                for (int mi = 0; mi < 2; mi++)
                    mma_tf32(c[mi][ni], a[mi], b0, b1);
            }
        }
        __syncthreads();
    }

    // ---- epilogue straight from registers (c0,c1 -> row; c2,c3 -> row+8)
#pragma unroll
    for (int mi = 0; mi < 2; mi++) {
#pragma unroll
        for (int half = 0; half < 2; half++) {
            const int row = m0 + warpM * 32 + mi * 16 + lr + half * 8;
            if (row >= M) continue;
            float* crow = C + (size_t)row * HID;
#pragma unroll
            for (int ni = 0; ni < 8; ni++) {
                const int col = warpN * 64 + ni * 8 + lc * 2;
                const float v0 = c[mi][ni][half * 2 + 0];
                const float v1 = c[mi][ni][half * 2 + 1];
                float2 o;
                if (EPI == EPI_NONE) {
                    o = make_float2(v0, v1);
                } else if (EPI == EPI_RELU) {
                    o.x = fmaxf(v0 + s_bias[col + 0], 0.f);
                    o.y = fmaxf(v1 + s_bias[col + 1], 0.f);
                } else { // EPI_GATE
                    float2 a0 = *(const float2*)(E0 + (size_t)row * HID + col);
                    float2 a1 = *(const float2*)(E1 + (size_t)row * HID + col);
                    const float g0 = 1.f / (1.f + __expf(-(v0 + s_bias[col + 0])));
                    const float g1 = 1.f / (1.f + __expf(-(v1 + s_bias[col + 1])));
                    o.x = fmaf(a1.x - a0.x, g0, a0.x);
                    o.y = fmaf(a1.y - a0.y, g1, a0.y);
                }
                *(float2*)(crow + col) = o;
            }
        }
    }
}

// ---------------- edge-index dtype sniff ----------------------------------------
__global__ void detect_idx(const unsigned int* __restrict__ p, int E2) {
    __shared__ int any;
    if (threadIdx.x == 0) any = 0;
    __syncthreads();
    int nsamp = E2 / 2; if (nsamp > 2048) nsamp = 2048;
    for (int i = threadIdx.x; i < nsamp; i += blockDim.x)
        if (p[2 * i + 1] != 0u) atomicOr(&any, 1);
    __syncthreads();
    if (threadIdx.x == 0) g_is64 = any ? 0 : 1;
}

__device__ __forceinline__ int edge_val(const void* ei, size_t idx) {
    return g_is64 ? (int)((const long long*)ei)[idx] : ((const int*)ei)[idx];
}

// ---------------- degree / CSR ---------------------------------------------------
__global__ void count_deg(const void* __restrict__ ei, int E) {
    int e = blockIdx.x * blockDim.x + threadIdx.x;
    if (e >= E) return;
    int d = edge_val(ei, (size_t)E + e);
    atomicAdd(&g_deg[d], 1);
}
__global__ void compute_dis(int n) {
    int i = blockIdx.x * blockDim.x + threadIdx.x;
    if (i < n) g_dis[i] = rsqrtf((float)(g_deg[i] + 1));
}
__global__ void scan1(int n) {
    __shared__ int sh[512];
    int i = blockIdx.x * 512 + threadIdx.x;
    sh[threadIdx.x] = (i < n) ? g_deg[i] : 0;
    __syncthreads();
    for (int off = 256; off > 0; off >>= 1) {
        if (threadIdx.x < off) sh[threadIdx.x] += sh[threadIdx.x + off];
        __syncthreads();
    }
    if (threadIdx.x == 0) g_bsum[blockIdx.x] = sh[0];
}
__global__ void scan2(int nb) {
    __shared__ int sh[1024];
    int tid = threadIdx.x;
    int v = (tid < nb) ? g_bsum[tid] : 0;
    sh[tid] = v;
    __syncthreads();
    for (int off = 1; off < 1024; off <<= 1) {
        int t = (tid >= off) ? sh[tid - off] : 0;
        __syncthreads();
        sh[tid] += t;
        __syncthreads();
    }
    if (tid < nb) g_bsum[tid] = sh[tid] - v;
}
__global__ void scan3(int n) {
    __shared__ int sh[512];
    int tid = threadIdx.x;
    int i = blockIdx.x * 512 + tid;
    int v = (i < n) ? g_deg[i] : 0;
    sh[tid] = v;
    __syncthreads();
    for (int off = 1; off < 512; off <<= 1) {
        int t = (tid >= off) ? sh[tid - off] : 0;
        __syncthreads();
        sh[tid] += t;
        __syncthreads();
    }
    if (i < n) {
        int rs = g_bsum[blockIdx.x] + sh[tid] - v;
        g_rowstart[i] = rs;
        g_cursor[i]   = rs;
    }
}
__global__ void fill_csr(const void* __restrict__ ei, int E) {
    int e = blockIdx.x * blockDim.x + threadIdx.x;
    if (e >= E) return;
    int s = edge_val(ei, e);
    int d = edge_val(ei, (size_t)E + e);
    int pos = atomicAdd(&g_cursor[d], 1);
    g_csr[pos] = s;
}

// ---------------- aggregation: warp per node, gather-sum -------------------------
__global__ void aggregate(const float* __restrict__ b_gcn, int n) {
    int gw   = (blockIdx.x * blockDim.x + threadIdx.x) >> 5;
    int lane = threadIdx.x & 31;
    if (gw >= n) return;
    const int node = gw;
    const float4* __restrict__ xg4 = (const float4*)g_xg;

    float4 selfv = xg4[(size_t)node * 32 + lane];
    float  dn    = g_dis[node];
    int    s0    = g_rowstart[node];
    int    cnt   = g_deg[node];

    float4 acc = make_float4(0.f, 0.f, 0.f, 0.f);
    int e = s0, eend = s0 + cnt;
    for (; e + 1 < eend; e += 2) {
        int s1 = g_csr[e], s2 = g_csr[e + 1];
        float w1 = g_dis[s1], w2 = g_dis[s2];
        float4 v1 = xg4[(size_t)s1 * 32 + lane];
        float4 v2 = xg4[(size_t)s2 * 32 + lane];
        acc.x += v1.x * w1 + v2.x * w2;
        acc.y += v1.y * w1 + v2.y * w2;
        acc.z += v1.z * w1 + v2.z * w2;
        acc.w += v1.w * w1 + v2.w * w2;
    }
    if (e < eend) {
        int s1 = g_csr[e];
        float w1 = g_dis[s1];
        float4 v1 = xg4[(size_t)s1 * 32 + lane];
        acc.x += v1.x * w1; acc.y += v1.y * w1;
        acc.z += v1.z * w1; acc.w += v1.w * w1;
    }
    const float sw = dn * dn;
    float4 b = ((const float4*)b_gcn)[lane];
    float4 o;
    o.x = fmaxf(acc.x * dn + selfv.x * sw + b.x, 0.f);
    o.y = fmaxf(acc.y * dn + selfv.y * sw + b.y, 0.f);
    o.z = fmaxf(acc.z * dn + selfv.z * sw + b.z, 0.f);
    o.w = fmaxf(acc.w * dn + selfv.w * sw + b.w, 0.f);
    ((float4*)g_diffused)[(size_t)node * 32 + lane] = o;
}

// ---------------- launcher --------------------------------------------------------
extern "C" void kernel_launch(void* const* d_in, const int* in_sizes, int n_in,
                              void* d_out, int out_size)
{
    const float* base   = (const float*)d_in[0];
    const float* ev     = (const float*)d_in[1];
    const void*  ei     = d_in[2];
    const float* W_proj = (const float*)d_in[3];
    const float* b_proj = (const float*)d_in[4];
    const float* W_gcn  = (const float*)d_in[5];
    const float* b_gcn  = (const float*)d_in[6];
    const float* W_gate = (const float*)d_in[7];
    const float* b_gate = (const float*)d_in[8];
    const float* W_fuse = (const float*)d_in[9];
    const float* b_fuse = (const float*)d_in[10];

    const int N = in_sizes[0] / HID;
    const int E = in_sizes[2] / 2;

    float *p_ef, *p_xg, *p_diff, *p_corr;
    int *p_deg;
    cudaGetSymbolAddress((void**)&p_ef,   g_event_feat);
    cudaGetSymbolAddress((void**)&p_xg,   g_xg);
    cudaGetSymbolAddress((void**)&p_diff, g_diffused);
    cudaGetSymbolAddress((void**)&p_corr, g_corrected);
    cudaGetSymbolAddress((void**)&p_deg,  g_deg);

    const int gT = (N + 127) / 128;
    const int gN = (N + 255) / 256;
    const int gE = (E + 255) / 256;
    const int nb = (N + 511) / 512;

    // launches 1-4: CSR prep (puts GEMMs at ncu capture slots 5/6)
    detect_idx<<<1, 256>>>((const unsigned int*)ei, 2 * E);
    cudaMemsetAsync(p_deg, 0, (size_t)N * sizeof(int));
    count_deg<<<gE, 256>>>(ei, E);
    compute_dis<<<gN, 256>>>(N);

    // 5: event_feat = relu(ev @ W_proj + b_proj)
    gemm_mma<64, 64, EPI_RELU><<<gT, 256>>>(ev, nullptr, W_proj, b_proj,
                                            nullptr, nullptr, p_ef, N);
    // 6: xg = event_feat @ W_gcn   (ncu capture target)
    gemm_mma<128, 128, EPI_NONE><<<gT, 256>>>(p_ef, nullptr, W_gcn, nullptr,
                                              nullptr, nullptr, p_xg, N);

    // CSR finalize
    scan1<<<nb, 512>>>(N);
    scan2<<<1, 1024>>>(nb);
    scan3<<<nb, 512>>>(N);
    fill_csr<<<gE, 256>>>(ei, E);

    // diffused = relu(A_norm @ xg + b_gcn)
    aggregate<<<(N * 32 + 255) / 256, 256>>>(b_gcn, N);

    // corrected = base*(1-g) + diffused*g,  g = sigmoid([base,diffused]@W_gate+b)
    gemm_mma<256, 128, EPI_GATE><<<gT, 256>>>(base, p_diff, W_gate, b_gate,
                                              base, p_diff, p_corr, N);
    // out = relu([base, corrected] @ W_fuse + b_fuse)
    gemm_mma<256, 128, EPI_RELU><<<gT, 256>>>(base, p_corr, W_fuse, b_fuse,
                                              nullptr, nullptr, (float*)d_out, N);
}

// round 5
// speedup vs baseline: 3.4177x; 1.0013x over previous
#include <cuda_runtime.h>
#include <cstdint>

#define NMAX 100000
#define EMAX 1600000
#define HID 128

// ---------------- scratch (device globals; no allocations allowed) ----------
__device__ float g_event_feat[(size_t)NMAX * HID];
__device__ float g_xg[(size_t)NMAX * HID];
__device__ float g_diffused[(size_t)NMAX * HID];
__device__ float g_corrected[(size_t)NMAX * HID];
__device__ int   g_deg[NMAX];
__device__ float g_dis[NMAX];
__device__ int   g_rowstart[NMAX];
__device__ int   g_cursor[NMAX];
__device__ int   g_csr[EMAX];
__device__ int   g_bsum[1024];
__device__ int   g_is64;
// transposed + k-permuted + tf32-pre-rounded weights [128 n][K k]
__device__ float g_wt_proj[128 * 64];
__device__ float g_wt_gcn [128 * 128];
__device__ float g_wt_gate[128 * 256];
__device__ float g_wt_fuse[128 * 256];

enum { EPI_RELU = 0, EPI_NONE = 1, EPI_GATE = 2 };

// ---------------- PTX helpers --------------------------------------------------
__device__ __forceinline__ uint32_t smem_u32(const void* p) {
    uint32_t a;
    asm("{ .reg .u64 t; cvta.to.shared.u64 t, %1; cvt.u32.u64 %0, t; }" : "=r"(a) : "l"(p));
    return a;
}
__device__ __forceinline__ void cp16(uint32_t dst, const void* src) {
    asm volatile("cp.async.cg.shared.global [%0], [%1], 16;" :: "r"(dst), "l"(src));
}
__device__ __forceinline__ void cp_commit() {
    asm volatile("cp.async.commit_group;" ::: "memory");
}
template<int N>
__device__ __forceinline__ void cp_wait() {
    asm volatile("cp.async.wait_group %0;" :: "n"(N) : "memory");
}
__device__ __forceinline__ uint32_t to_tf32(float f) {
    uint32_t u;
    asm("cvt.rna.tf32.f32 %0, %1;" : "=r"(u) : "f"(f));
    return u;
}
__device__ __forceinline__ void mma_tf32(float* c, const uint32_t* a, uint32_t b0, uint32_t b1) {
    asm volatile(
        "mma.sync.aligned.m16n8k8.row.col.f32.tf32.tf32.f32 "
        "{%0,%1,%2,%3}, {%4,%5,%6,%7}, {%8,%9}, {%0,%1,%2,%3};"
        : "+f"(c[0]), "+f"(c[1]), "+f"(c[2]), "+f"(c[3])
        : "r"(a[0]), "r"(a[1]), "r"(a[2]), "r"(a[3]), "r"(b0), "r"(b1));
}

// ---------------- weight prep: Wt[n][perm(k)] = tf32_rna(W[k][n]) ---------------
// perm within each 16-group puts (k, k+4) adjacent: q<4->2q | q<8->2(q-4)+1 |
// q<12->8+2(q-8) | else 8+2(q-12)+1.  One kernel handles all four weights.
__device__ __forceinline__ int pos16(int q) {
    return (q < 4) ? 2 * q
         : (q < 8) ? 2 * (q - 4) + 1
         : (q < 12) ? 8 + 2 * (q - 8)
         : 8 + 2 * (q - 12) + 1;
}
__global__ void wprep(const float* __restrict__ W0, const float* __restrict__ W1,
                      const float* __restrict__ W2, const float* __restrict__ W3,
                      float* __restrict__ T0, float* __restrict__ T1,
                      float* __restrict__ T2, float* __restrict__ T3)
{
    __shared__ float s[32][33];
    int b = blockIdx.x;
    const float* W; float* T; int K;
    if (b < 8)       { W = W0; T = T0; K = 64;  }
    else if (b < 24) { W = W1; T = T1; K = 128; b -= 8;  }
    else if (b < 56) { W = W2; T = T2; K = 256; b -= 24; }
    else             { W = W3; T = T3; K = 256; b -= 56; }
    const int k0 = (b >> 2) * 32, n0 = (b & 3) * 32;
    const int tx = threadIdx.x & 31, ty = threadIdx.x >> 5;   // 256 thr: ty 0..7
#pragma unroll
    for (int i = 0; i < 4; i++)
        s[ty + i * 8][tx] = W[(size_t)(k0 + ty + i * 8) * HID + n0 + tx];
    __syncthreads();
    const int k = k0 + tx;
    const int q = k & 15;
    const int col = (k - q) + pos16(q);
#pragma unroll
    for (int i = 0; i < 4; i++) {
        const int n = n0 + ty + i * 8;
        T[(size_t)n * K + col] = __uint_as_float(to_tf32(s[tx][ty + i * 8]));
    }
}

// ---------------- mma.sync tf32 GEMM --------------------------------------------
// C[M,128] = epi( concat(A0[:,0:K0], A1[:,K0:KTOT]) @ W[KTOT,128] + bias )
// Wt: prepped weight [128][KTOT]. 256 thr = 8 warps; tile 128x128; BK=16, 2-stage.
template<int KTOT, int K0, int EPI>
__global__ void __launch_bounds__(256, 2)
gemm_mma(const float* __restrict__ A0, const float* __restrict__ A1,
         const float* __restrict__ Wt, const float* __restrict__ bias,
         const float* __restrict__ E0, const float* __restrict__ E1,
         float* __restrict__ C, int M)
{
    constexpr int BK   = 16;
    constexpr int NCH  = KTOT / BK;
    constexpr int LDA  = 20;   // floats; conflict-free scalar A-frag loads
    constexpr int LDB2 = 24;   // floats; conflict-free LDS.64 B-frag loads

    __shared__ __align__(16) float As[2][128 * LDA];   // 2 x 10240 B
    __shared__ __align__(16) float Bs[2][128 * LDB2];  // 2 x 12288 B
    __shared__ float s_bias[HID];

    const int tid   = threadIdx.x;
    const int wid   = tid >> 5;
    const int lane  = tid & 31;
    const int warpM = wid & 3;
    const int warpN = wid >> 2;
    const int lr    = lane >> 2;   // 0..7
    const int lc    = lane & 3;    // 0..3
    const int m0    = blockIdx.x * 128;

    if (EPI != EPI_NONE && tid < HID) s_bias[tid] = bias[tid];

    const uint32_t as_u[2] = { smem_u32(&As[0][0]), smem_u32(&As[1][0]) };
    const uint32_t bs_u[2] = { smem_u32(&Bs[0][0]), smem_u32(&Bs[1][0]) };

    float c[2][8][4];
#pragma unroll
    for (int mi = 0; mi < 2; mi++)
#pragma unroll
        for (int ni = 0; ni < 8; ni++)
#pragma unroll
            for (int j = 0; j < 4; j++) c[mi][ni][j] = 0.f;

    // ---- async copy of one K-chunk into stage s
    auto issue = [&](int s, int ch) {
        const int kc = ch * BK;
        const float* Ap; int stride, kc2;
        if (KTOT == K0 || kc < K0) { Ap = A0; stride = K0;        kc2 = kc; }
        else                       { Ap = A1; stride = KTOT - K0; kc2 = kc - K0; }
        // A: 128 rows x 16 floats = 512 x 16B
#pragma unroll
        for (int i = 0; i < 2; i++) {
            const int idx = tid + i * 256;
            const int r = idx >> 2, q = idx & 3;
            int gr = m0 + r; if (gr > M - 1) gr = M - 1;
            cp16(as_u[s] + (uint32_t)(r * LDA + q * 4) * 4,
                 Ap + (size_t)gr * stride + kc2 + q * 4);
        }
        // B: 128 n-rows x 16 floats = 512 x 16B (k-permuted in Wt)
#pragma unroll
        for (int i = 0; i < 2; i++) {
            const int idx = tid + i * 256;
            const int n = idx >> 2, q = idx & 3;
            cp16(bs_u[s] + (uint32_t)(n * LDB2 + q * 4) * 4,
                 Wt + (size_t)n * KTOT + kc + q * 4);
        }
        cp_commit();
    };

    issue(0, 0);

    for (int ch = 0; ch < NCH; ch++) {
        const int s = ch & 1;
        if (ch + 1 < NCH) { issue(s ^ 1, ch + 1); cp_wait<1>(); }
        else              { cp_wait<0>(); }
        __syncthreads();

#pragma unroll
        for (int ks = 0; ks < 2; ks++) {
            const int k = ks * 8 + lc;
            uint32_t a[2][4];
#pragma unroll
            for (int mi = 0; mi < 2; mi++) {
                const int row = warpM * 32 + mi * 16 + lr;
                a[mi][0] = to_tf32(As[s][row * LDA + k]);
                a[mi][1] = to_tf32(As[s][(row + 8) * LDA + k]);
                a[mi][2] = to_tf32(As[s][row * LDA + k + 4]);
                a[mi][3] = to_tf32(As[s][(row + 8) * LDA + k + 4]);
            }
#pragma unroll
            for (int ni = 0; ni < 8; ni++) {
                const int n = warpN * 64 + ni * 8 + lr;
                // permuted layout: (k, k+4) adjacent at offset ks*8 + 2*lc
                const float2 bp = *(const float2*)&Bs[s][n * LDB2 + ks * 8 + 2 * lc];
                const uint32_t b0 = __float_as_uint(bp.x);
                const uint32_t b1 = __float_as_uint(bp.y);
#pragma unroll
                for (int mi = 0; mi < 2; mi++)
                    mma_tf32(c[mi][ni], a[mi], b0, b1);
            }
        }
        __syncthreads();
    }

    // ---- epilogue straight from registers
#pragma unroll
    for (int mi = 0; mi < 2; mi++) {
#pragma unroll
        for (int half = 0; half < 2; half++) {
            const int row = m0 + warpM * 32 + mi * 16 + lr + half * 8;
            if (row >= M) continue;
            float* crow = C + (size_t)row * HID;
#pragma unroll
            for (int ni = 0; ni < 8; ni++) {
                const int col = warpN * 64 + ni * 8 + lc * 2;
                const float v0 = c[mi][ni][half * 2 + 0];
                const float v1 = c[mi][ni][half * 2 + 1];
                float2 o;
                if (EPI == EPI_NONE) {
                    o = make_float2(v0, v1);
                } else if (EPI == EPI_RELU) {
                    o.x = fmaxf(v0 + s_bias[col + 0], 0.f);
                    o.y = fmaxf(v1 + s_bias[col + 1], 0.f);
                } else { // EPI_GATE
                    float2 a0 = *(const float2*)(E0 + (size_t)row * HID + col);
                    float2 a1 = *(const float2*)(E1 + (size_t)row * HID + col);
                    const float g0 = 1.f / (1.f + __expf(-(v0 + s_bias[col + 0])));
                    const float g1 = 1.f / (1.f + __expf(-(v1 + s_bias[col + 1])));
                    o.x = fmaf(a1.x - a0.x, g0, a0.x);
                    o.y = fmaf(a1.y - a0.y, g1, a0.y);
                }
                *(float2*)(crow + col) = o;
            }
        }
    }
}

// ---------------- edge-index dtype sniff ----------------------------------------
__global__ void detect_idx(const unsigned int* __restrict__ p, int E2) {
    __shared__ int any;
    if (threadIdx.x == 0) any = 0;
    __syncthreads();
    int nsamp = E2 / 2; if (nsamp > 2048) nsamp = 2048;
    for (int i = threadIdx.x; i < nsamp; i += blockDim.x)
        if (p[2 * i + 1] != 0u) atomicOr(&any, 1);
    __syncthreads();
    if (threadIdx.x == 0) g_is64 = any ? 0 : 1;
}

__device__ __forceinline__ int edge_val(const void* ei, size_t idx) {
    return g_is64 ? (int)((const long long*)ei)[idx] : ((const int*)ei)[idx];
}

// ---------------- degree / CSR ---------------------------------------------------
__global__ void count_deg(const void* __restrict__ ei, int E) {
    int e = blockIdx.x * blockDim.x + threadIdx.x;
    if (e >= E) return;
    int d = edge_val(ei, (size_t)E + e);
    atomicAdd(&g_deg[d], 1);
}
// scan stage 1 (+ fused dis = rsqrt(deg+1))
__global__ void scan1(int n) {
    __shared__ int sh[512];
    int i = blockIdx.x * 512 + threadIdx.x;
    int v = (i < n) ? g_deg[i] : 0;
    if (i < n) g_dis[i] = rsqrtf((float)(v + 1));
    sh[threadIdx.x] = v;
    __syncthreads();
    for (int off = 256; off > 0; off >>= 1) {
        if (threadIdx.x < off) sh[threadIdx.x] += sh[threadIdx.x + off];
        __syncthreads();
    }
    if (threadIdx.x == 0) g_bsum[blockIdx.x] = sh[0];
}
__global__ void scan2(int nb) {
    __shared__ int sh[1024];
    int tid = threadIdx.x;
    int v = (tid < nb) ? g_bsum[tid] : 0;
    sh[tid] = v;
    __syncthreads();
    for (int off = 1; off < 1024; off <<= 1) {
        int t = (tid >= off) ? sh[tid - off] : 0;
        __syncthreads();
        sh[tid] += t;
        __syncthreads();
    }
    if (tid < nb) g_bsum[tid] = sh[tid] - v;
}
__global__ void scan3(int n) {
    __shared__ int sh[512];
    int tid = threadIdx.x;
    int i = blockIdx.x * 512 + tid;
    int v = (i < n) ? g_deg[i] : 0;
    sh[tid] = v;
    __syncthreads();
    for (int off = 1; off < 512; off <<= 1) {
        int t = (tid >= off) ? sh[tid - off] : 0;
        __syncthreads();
        sh[tid] += t;
        __syncthreads();
    }
    if (i < n) {
        int rs = g_bsum[blockIdx.x] + sh[tid] - v;
        g_rowstart[i] = rs;
        g_cursor[i]   = rs;
    }
}
__global__ void fill_csr(const void* __restrict__ ei, int E) {
    int e = blockIdx.x * blockDim.x + threadIdx.x;
    if (e >= E) return;
    int s = edge_val(ei, e);
    int d = edge_val(ei, (size_t)E + e);
    int pos = atomicAdd(&g_cursor[d], 1);
    g_csr[pos] = s;
}

// ---------------- aggregation: warp per node, gather-sum -------------------------
__global__ void aggregate(const float* __restrict__ b_gcn, int n) {
    int gw   = (blockIdx.x * blockDim.x + threadIdx.x) >> 5;
    int lane = threadIdx.x & 31;
    if (gw >= n) return;
    const int node = gw;
    const float4* __restrict__ xg4 = (const float4*)g_xg;

    float4 selfv = xg4[(size_t)node * 32 + lane];
    float  dn    = g_dis[node];
    int    s0    = g_rowstart[node];
    int    cnt   = g_deg[node];

    float4 acc = make_float4(0.f, 0.f, 0.f, 0.f);
    int e = s0, eend = s0 + cnt;
    for (; e + 1 < eend; e += 2) {
        int s1 = g_csr[e], s2 = g_csr[e + 1];
        float w1 = g_dis[s1], w2 = g_dis[s2];
        float4 v1 = xg4[(size_t)s1 * 32 + lane];
        float4 v2 = xg4[(size_t)s2 * 32 + lane];
        acc.x += v1.x * w1 + v2.x * w2;
        acc.y += v1.y * w1 + v2.y * w2;
        acc.z += v1.z * w1 + v2.z * w2;
        acc.w += v1.w * w1 + v2.w * w2;
    }
    if (e < eend) {
        int s1 = g_csr[e];
        float w1 = g_dis[s1];
        float4 v1 = xg4[(size_t)s1 * 32 + lane];
        acc.x += v1.x * w1; acc.y += v1.y * w1;
        acc.z += v1.z * w1; acc.w += v1.w * w1;
    }
    const float sw = dn * dn;
    float4 b = ((const float4*)b_gcn)[lane];
    float4 o;
    o.x = fmaxf(acc.x * dn + selfv.x * sw + b.x, 0.f);
    o.y = fmaxf(acc.y * dn + selfv.y * sw + b.y, 0.f);
    o.z = fmaxf(acc.z * dn + selfv.z * sw + b.z, 0.f);
    o.w = fmaxf(acc.w * dn + selfv.w * sw + b.w, 0.f);
    ((float4*)g_diffused)[(size_t)node * 32 + lane] = o;
}

// ---------------- launcher --------------------------------------------------------
extern "C" void kernel_launch(void* const* d_in, const int* in_sizes, int n_in,
                              void* d_out, int out_size)
{
    const float* base   = (const float*)d_in[0];
    const float* ev     = (const float*)d_in[1];
    const void*  ei     = d_in[2];
    const float* W_proj = (const float*)d_in[3];
    const float* b_proj = (const float*)d_in[4];
    const float* W_gcn  = (const float*)d_in[5];
    const float* b_gcn  = (const float*)d_in[6];
    const float* W_gate = (const float*)d_in[7];
    const float* b_gate = (const float*)d_in[8];
    const float* W_fuse = (const float*)d_in[9];
    const float* b_fuse = (const float*)d_in[10];

    const int N = in_sizes[0] / HID;
    const int E = in_sizes[2] / 2;

    float *p_ef, *p_xg, *p_diff, *p_corr;
    float *p_wtp, *p_wtg, *p_wtga, *p_wtf;
    int *p_deg;
    cudaGetSymbolAddress((void**)&p_ef,   g_event_feat);
    cudaGetSymbolAddress((void**)&p_xg,   g_xg);
    cudaGetSymbolAddress((void**)&p_diff, g_diffused);
    cudaGetSymbolAddress((void**)&p_corr, g_corrected);
    cudaGetSymbolAddress((void**)&p_wtp,  g_wt_proj);
    cudaGetSymbolAddress((void**)&p_wtg,  g_wt_gcn);
    cudaGetSymbolAddress((void**)&p_wtga, g_wt_gate);
    cudaGetSymbolAddress((void**)&p_wtf,  g_wt_fuse);
    cudaGetSymbolAddress((void**)&p_deg,  g_deg);

    const int gT = (N + 127) / 128;
    const int gE = (E + 255) / 256;
    const int nb = (N + 511) / 512;

    // prep + CSR front (keeps proj GEMM at the ncu capture slot)
    detect_idx<<<1, 256>>>((const unsigned int*)ei, 2 * E);
    cudaMemsetAsync(p_deg, 0, (size_t)N * sizeof(int));
    wprep<<<88, 256>>>(W_proj, W_gcn, W_gate, W_fuse, p_wtp, p_wtg, p_wtga, p_wtf);
    count_deg<<<gE, 256>>>(ei, E);

    // event_feat = relu(ev @ W_proj + b_proj)
    gemm_mma<64, 64, EPI_RELU><<<gT, 256>>>(ev, nullptr, p_wtp, b_proj,
                                            nullptr, nullptr, p_ef, N);
    // xg = event_feat @ W_gcn
    gemm_mma<128, 128, EPI_NONE><<<gT, 256>>>(p_ef, nullptr, p_wtg, nullptr,
                                              nullptr, nullptr, p_xg, N);

    // CSR finalize (scan1 also computes dis)
    scan1<<<nb, 512>>>(N);
    scan2<<<1, 1024>>>(nb);
    scan3<<<nb, 512>>>(N);
    fill_csr<<<gE, 256>>>(ei, E);

    // diffused = relu(A_norm @ xg + b_gcn)
    aggregate<<<(N * 32 + 255) / 256, 256>>>(b_gcn, N);

    // corrected = base*(1-g) + diffused*g,  g = sigmoid([base,diffused]@W_gate+b)
    gemm_mma<256, 128, EPI_GATE><<<gT, 256>>>(base, p_diff, p_wtga, b_gate,
                                              base, p_diff, p_corr, N);
    // out = relu([base, corrected] @ W_fuse + b_fuse)
    gemm_mma<256, 128, EPI_RELU><<<gT, 256>>>(base, p_corr, p_wtf, b_fuse,
                                              nullptr, nullptr, (float*)d_out, N);
}

// round 6
// speedup vs baseline: 3.7619x; 1.1007x over previous
#include <cuda_runtime.h>
#include <cstdint>

#define NMAX 100000
#define EMAX 1600000
#define HID 128

// ---------------- scratch (device globals; no allocations allowed) ----------
__device__ float g_xg[(size_t)NMAX * HID];
__device__ float g_diffused[(size_t)NMAX * HID];
__device__ int   g_deg[NMAX];
__device__ float g_dis[NMAX];
__device__ int   g_rowstart[NMAX];
__device__ int   g_cursor[NMAX];
__device__ int   g_csr[EMAX];
__device__ int   g_bsum[1024];
__device__ int   g_is64;
// transposed + k-permuted + tf32-pre-rounded weights [128 n][K k]
__device__ float g_wt_proj[128 * 64];
__device__ float g_wt_gcn [128 * 128];
__device__ float g_wt_gate[128 * 256];
__device__ float g_wt_fuse[128 * 256];

// ---------------- PTX helpers --------------------------------------------------
__device__ __forceinline__ uint32_t smem_u32(const void* p) {
    uint32_t a;
    asm("{ .reg .u64 t; cvta.to.shared.u64 t, %1; cvt.u32.u64 %0, t; }" : "=r"(a) : "l"(p));
    return a;
}
__device__ __forceinline__ void cp16(uint32_t dst, const void* src) {
    asm volatile("cp.async.cg.shared.global [%0], [%1], 16;" :: "r"(dst), "l"(src));
}
__device__ __forceinline__ void cp_commit() {
    asm volatile("cp.async.commit_group;" ::: "memory");
}
template<int N>
__device__ __forceinline__ void cp_wait() {
    asm volatile("cp.async.wait_group %0;" :: "n"(N) : "memory");
}
__device__ __forceinline__ uint32_t to_tf32(float f) {
    uint32_t u;
    asm("cvt.rna.tf32.f32 %0, %1;" : "=r"(u) : "f"(f));
    return u;
}
__device__ __forceinline__ void mma_tf32(float* c, const uint32_t* a, uint32_t b0, uint32_t b1) {
    asm volatile(
        "mma.sync.aligned.m16n8k8.row.col.f32.tf32.tf32.f32 "
        "{%0,%1,%2,%3}, {%4,%5,%6,%7}, {%8,%9}, {%0,%1,%2,%3};"
        : "+f"(c[0]), "+f"(c[1]), "+f"(c[2]), "+f"(c[3])
        : "r"(a[0]), "r"(a[1]), "r"(a[2]), "r"(a[3]), "r"(b0), "r"(b1));
}

// tile geometry shared by both fused kernels
#define LDA  20     // A stage stride (floats) — conflict-free scalar loads
#define LDB2 24     // B stage stride (floats) — conflict-free LDS.64
#define LDE  132    // resident tile stride (floats) — conflict-free A-frag loads
#define SMEM_FLOATS (128 * LDE + 2 * 128 * LDA + 2 * 128 * LDB2 + 256)
#define SMEM_BYTES  (SMEM_FLOATS * 4)

// ---------------- weight prep: Wt[n][perm(k)] = tf32_rna(W[k][n]) ---------------
__device__ __forceinline__ int pos16(int q) {
    return (q < 4) ? 2 * q
         : (q < 8) ? 2 * (q - 4) + 1
         : (q < 12) ? 8 + 2 * (q - 8)
         : 8 + 2 * (q - 12) + 1;
}
__global__ void wprep(const float* __restrict__ W0, const float* __restrict__ W1,
                      const float* __restrict__ W2, const float* __restrict__ W3,
                      float* __restrict__ T0, float* __restrict__ T1,
                      float* __restrict__ T2, float* __restrict__ T3)
{
    __shared__ float s[32][33];
    int b = blockIdx.x;
    const float* W; float* T; int K;
    if (b < 8)       { W = W0; T = T0; K = 64;  }
    else if (b < 24) { W = W1; T = T1; K = 128; b -= 8;  }
    else if (b < 56) { W = W2; T = T2; K = 256; b -= 24; }
    else             { W = W3; T = T3; K = 256; b -= 56; }
    const int k0 = (b >> 2) * 32, n0 = (b & 3) * 32;
    const int tx = threadIdx.x & 31, ty = threadIdx.x >> 5;
#pragma unroll
    for (int i = 0; i < 4; i++)
        s[ty + i * 8][tx] = W[(size_t)(k0 + ty + i * 8) * HID + n0 + tx];
    __syncthreads();
    const int k = k0 + tx;
    const int q = k & 15;
    const int col = (k - q) + pos16(q);
#pragma unroll
    for (int i = 0; i < 4; i++) {
        const int n = n0 + ty + i * 8;
        T[(size_t)n * K + col] = __uint_as_float(to_tf32(s[tx][ty + i * 8]));
    }
}

// ================================================================================
// Fused kernel 1: ef = relu(ev @ Wp + bp) [smem-resident] ; xg = ef @ Wgcn
// ================================================================================
__global__ void __launch_bounds__(256, 2)
k_proj_gcn(const float* __restrict__ ev, const float* __restrict__ Wtp,
           const float* __restrict__ bp, const float* __restrict__ Wtg,
           float* __restrict__ xg, int M)
{
    extern __shared__ float dsm[];
    float* ef = dsm;                       // 128 * LDE
    float* As = dsm + 128 * LDE;           // 2 * 128 * LDA
    float* Bs = As + 2 * 128 * LDA;        // 2 * 128 * LDB2
    float* sb = Bs + 2 * 128 * LDB2;       // 128

    const int tid   = threadIdx.x;
    const int wid   = tid >> 5, lane = tid & 31;
    const int warpM = wid & 3,  warpN = wid >> 2;
    const int lr    = lane >> 2, lc = lane & 3;
    const int m0    = blockIdx.x * 128;

    if (tid < 128) sb[tid] = bp[tid];

    const uint32_t as_u[2] = { smem_u32(As), smem_u32(As + 128 * LDA) };
    const uint32_t bs_u[2] = { smem_u32(Bs), smem_u32(Bs + 128 * LDB2) };

    float c[2][8][4];
#pragma unroll
    for (int mi = 0; mi < 2; mi++)
#pragma unroll
        for (int ni = 0; ni < 8; ni++)
#pragma unroll
            for (int j = 0; j < 4; j++) c[mi][ni][j] = 0.f;

    auto issueA1 = [&](int s, int ch) {
        const int kc = ch * 16;
#pragma unroll
        for (int i = 0; i < 2; i++) {
            const int idx = tid + i * 256;
            const int r = idx >> 2, q = idx & 3;
            int gr = m0 + r; if (gr > M - 1) gr = M - 1;
            cp16(as_u[s] + (uint32_t)(r * LDA + q * 4) * 4,
                 ev + (size_t)gr * 64 + kc + q * 4);
        }
    };
    auto issueB = [&](int s, int ch, const float* Wt, int KT) {
        const int kc = ch * 16;
#pragma unroll
        for (int i = 0; i < 2; i++) {
            const int idx = tid + i * 256;
            const int n = idx >> 2, q = idx & 3;
            cp16(bs_u[s] + (uint32_t)(n * LDB2 + q * 4) * 4,
                 Wt + (size_t)n * KT + kc + q * 4);
        }
    };
    auto compute = [&](int s) {
        const float* as = As + s * 128 * LDA;
        const float* bs = Bs + s * 128 * LDB2;
#pragma unroll
        for (int ks = 0; ks < 2; ks++) {
            const int k = ks * 8 + lc;
            uint32_t a[2][4];
#pragma unroll
            for (int mi = 0; mi < 2; mi++) {
                const int row = warpM * 32 + mi * 16 + lr;
                a[mi][0] = to_tf32(as[row * LDA + k]);
                a[mi][1] = to_tf32(as[(row + 8) * LDA + k]);
                a[mi][2] = to_tf32(as[row * LDA + k + 4]);
                a[mi][3] = to_tf32(as[(row + 8) * LDA + k + 4]);
            }
#pragma unroll
            for (int ni = 0; ni < 8; ni++) {
                const int n = warpN * 64 + ni * 8 + lr;
                const float2 bp2 = *(const float2*)&bs[n * LDB2 + ks * 8 + 2 * lc];
#pragma unroll
                for (int mi = 0; mi < 2; mi++)
                    mma_tf32(c[mi][ni], a[mi], __float_as_uint(bp2.x), __float_as_uint(bp2.y));
            }
        }
    };

    // ---- phase 1: K=64, 4 chunks
    issueA1(0, 0); issueB(0, 0, Wtp, 64); cp_commit();
    for (int ch = 0; ch < 4; ch++) {
        const int s = ch & 1;
        if (ch < 3) { issueA1(s ^ 1, ch + 1); issueB(s ^ 1, ch + 1, Wtp, 64); cp_commit(); cp_wait<1>(); }
        else        { cp_wait<0>(); }
        __syncthreads();
        compute(s);
        __syncthreads();
    }

    // prefetch phase-2 B chunk 0 behind the epilogue
    issueB(0, 0, Wtg, 128); cp_commit();

    // ---- epilogue 1: relu(v+b) -> tf32 bits into ef smem
#pragma unroll
    for (int mi = 0; mi < 2; mi++)
#pragma unroll
        for (int half = 0; half < 2; half++) {
            const int row = warpM * 32 + mi * 16 + lr + half * 8;
#pragma unroll
            for (int ni = 0; ni < 8; ni++) {
                const int col = warpN * 64 + ni * 8 + lc * 2;
                const float v0 = fmaxf(c[mi][ni][half * 2 + 0] + sb[col + 0], 0.f);
                const float v1 = fmaxf(c[mi][ni][half * 2 + 1] + sb[col + 1], 0.f);
                *(float2*)&ef[row * LDE + col] =
                    make_float2(__uint_as_float(to_tf32(v0)), __uint_as_float(to_tf32(v1)));
            }
        }
    __syncthreads();

#pragma unroll
    for (int mi = 0; mi < 2; mi++)
#pragma unroll
        for (int ni = 0; ni < 8; ni++)
#pragma unroll
            for (int j = 0; j < 4; j++) c[mi][ni][j] = 0.f;

    // ---- phase 2: xg = ef @ Wgcn, K=128, A resident in smem
    for (int ch = 0; ch < 8; ch++) {
        const int s = ch & 1;
        if (ch < 7) { issueB(s ^ 1, ch + 1, Wtg, 128); cp_commit(); cp_wait<1>(); }
        else        { cp_wait<0>(); }
        __syncthreads();
        const float* bs = Bs + s * 128 * LDB2;
#pragma unroll
        for (int ks = 0; ks < 2; ks++) {
            const int k = ch * 16 + ks * 8 + lc;
            uint32_t a[2][4];
#pragma unroll
            for (int mi = 0; mi < 2; mi++) {
                const int row = warpM * 32 + mi * 16 + lr;
                a[mi][0] = __float_as_uint(ef[row * LDE + k]);
                a[mi][1] = __float_as_uint(ef[(row + 8) * LDE + k]);
                a[mi][2] = __float_as_uint(ef[row * LDE + k + 4]);
                a[mi][3] = __float_as_uint(ef[(row + 8) * LDE + k + 4]);
            }
#pragma unroll
            for (int ni = 0; ni < 8; ni++) {
                const int n = warpN * 64 + ni * 8 + lr;
                const float2 bp2 = *(const float2*)&bs[n * LDB2 + ks * 8 + 2 * lc];
#pragma unroll
                for (int mi = 0; mi < 2; mi++)
                    mma_tf32(c[mi][ni], a[mi], __float_as_uint(bp2.x), __float_as_uint(bp2.y));
            }
        }
        __syncthreads();
    }

    // ---- epilogue 2: xg (no activation)
#pragma unroll
    for (int mi = 0; mi < 2; mi++)
#pragma unroll
        for (int half = 0; half < 2; half++) {
            const int row = m0 + warpM * 32 + mi * 16 + lr + half * 8;
            if (row >= M) continue;
#pragma unroll
            for (int ni = 0; ni < 8; ni++) {
                const int col = warpN * 64 + ni * 8 + lc * 2;
                *(float2*)(xg + (size_t)row * HID + col) =
                    make_float2(c[mi][ni][half * 2 + 0], c[mi][ni][half * 2 + 1]);
            }
        }
}

// ================================================================================
// Fused kernel 2: gate = sigmoid([base,diff]@Wg+bg); corr = mix [smem];
//                 out = relu([base,corr]@Wf+bf)
// ================================================================================
__global__ void __launch_bounds__(256, 2)
k_gate_fuse(const float* __restrict__ base, const float* __restrict__ diff,
            const float* __restrict__ Wtg, const float* __restrict__ bg,
            const float* __restrict__ Wtf, const float* __restrict__ bf,
            float* __restrict__ out, int M)
{
    extern __shared__ float dsm[];
    float* corr = dsm;
    float* As   = dsm + 128 * LDE;
    float* Bs   = As + 2 * 128 * LDA;
    float* sbg  = Bs + 2 * 128 * LDB2;
    float* sbf  = sbg + 128;

    const int tid   = threadIdx.x;
    const int wid   = tid >> 5, lane = tid & 31;
    const int warpM = wid & 3,  warpN = wid >> 2;
    const int lr    = lane >> 2, lc = lane & 3;
    const int m0    = blockIdx.x * 128;

    if (tid < 128) { sbg[tid] = bg[tid]; sbf[tid] = bf[tid]; }

    const uint32_t as_u[2] = { smem_u32(As), smem_u32(As + 128 * LDA) };
    const uint32_t bs_u[2] = { smem_u32(Bs), smem_u32(Bs + 128 * LDB2) };

    float c[2][8][4];
#pragma unroll
    for (int mi = 0; mi < 2; mi++)
#pragma unroll
        for (int ni = 0; ni < 8; ni++)
#pragma unroll
            for (int j = 0; j < 4; j++) c[mi][ni][j] = 0.f;

    auto issueA = [&](int s, int ch) {   // gate phase: ch<8 base, else diff
        const float* Ap = (ch < 8) ? base : diff;
        const int kc = (ch < 8) ? ch * 16 : (ch - 8) * 16;
#pragma unroll
        for (int i = 0; i < 2; i++) {
            const int idx = tid + i * 256;
            const int r = idx >> 2, q = idx & 3;
            int gr = m0 + r; if (gr > M - 1) gr = M - 1;
            cp16(as_u[s] + (uint32_t)(r * LDA + q * 4) * 4,
                 Ap + (size_t)gr * HID + kc + q * 4);
        }
    };
    auto issueAbase = [&](int s, int ch) {  // fuse phase ch<8: base
        const int kc = ch * 16;
#pragma unroll
        for (int i = 0; i < 2; i++) {
            const int idx = tid + i * 256;
            const int r = idx >> 2, q = idx & 3;
            int gr = m0 + r; if (gr > M - 1) gr = M - 1;
            cp16(as_u[s] + (uint32_t)(r * LDA + q * 4) * 4,
                 base + (size_t)gr * HID + kc + q * 4);
        }
    };
    auto issueB = [&](int s, int ch, const float* Wt) {
        const int kc = ch * 16;
#pragma unroll
        for (int i = 0; i < 2; i++) {
            const int idx = tid + i * 256;
            const int n = idx >> 2, q = idx & 3;
            cp16(bs_u[s] + (uint32_t)(n * LDB2 + q * 4) * 4,
                 Wt + (size_t)n * 256 + kc + q * 4);
        }
    };
    auto computeA = [&](int s) {   // A from stage buffers (with cvt)
        const float* as = As + s * 128 * LDA;
        const float* bs = Bs + s * 128 * LDB2;
#pragma unroll
        for (int ks = 0; ks < 2; ks++) {
            const int k = ks * 8 + lc;
            uint32_t a[2][4];
#pragma unroll
            for (int mi = 0; mi < 2; mi++) {
                const int row = warpM * 32 + mi * 16 + lr;
                a[mi][0] = to_tf32(as[row * LDA + k]);
                a[mi][1] = to_tf32(as[(row + 8) * LDA + k]);
                a[mi][2] = to_tf32(as[row * LDA + k + 4]);
                a[mi][3] = to_tf32(as[(row + 8) * LDA + k + 4]);
            }
#pragma unroll
            for (int ni = 0; ni < 8; ni++) {
                const int n = warpN * 64 + ni * 8 + lr;
                const float2 bp2 = *(const float2*)&bs[n * LDB2 + ks * 8 + 2 * lc];
#pragma unroll
                for (int mi = 0; mi < 2; mi++)
                    mma_tf32(c[mi][ni], a[mi], __float_as_uint(bp2.x), __float_as_uint(bp2.y));
            }
        }
    };

    // ---- phase A: gate GEMM, K=256 (16 chunks)
    issueA(0, 0); issueB(0, 0, Wtg); cp_commit();
    for (int ch = 0; ch < 16; ch++) {
        const int s = ch & 1;
        if (ch < 15) { issueA(s ^ 1, ch + 1); issueB(s ^ 1, ch + 1, Wtg); cp_commit(); cp_wait<1>(); }
        else         { cp_wait<0>(); }
        __syncthreads();
        computeA(s);
        __syncthreads();
    }

    // prefetch fuse chunk 0 behind the gate epilogue
    issueAbase(0, 0); issueB(0, 0, Wtf); cp_commit();

    // ---- gate epilogue: corrected tile -> smem (tf32 bits)
#pragma unroll
    for (int mi = 0; mi < 2; mi++)
#pragma unroll
        for (int half = 0; half < 2; half++) {
            const int lrow = warpM * 32 + mi * 16 + lr + half * 8;
            const int row  = m0 + lrow;
            if (row >= M) continue;
#pragma unroll
            for (int ni = 0; ni < 8; ni++) {
                const int col = warpN * 64 + ni * 8 + lc * 2;
                const float2 a0 = *(const float2*)(base + (size_t)row * HID + col);
                const float2 a1 = *(const float2*)(diff + (size_t)row * HID + col);
                const float g0 = 1.f / (1.f + __expf(-(c[mi][ni][half * 2 + 0] + sbg[col + 0])));
                const float g1 = 1.f / (1.f + __expf(-(c[mi][ni][half * 2 + 1] + sbg[col + 1])));
                const float v0 = fmaf(a1.x - a0.x, g0, a0.x);
                const float v1 = fmaf(a1.y - a0.y, g1, a0.y);
                *(float2*)&corr[lrow * LDE + col] =
                    make_float2(__uint_as_float(to_tf32(v0)), __uint_as_float(to_tf32(v1)));
            }
        }
    __syncthreads();

#pragma unroll
    for (int mi = 0; mi < 2; mi++)
#pragma unroll
        for (int ni = 0; ni < 8; ni++)
#pragma unroll
            for (int j = 0; j < 4; j++) c[mi][ni][j] = 0.f;

    // ---- phase B: fuse GEMM, K=256; ch<8 A=base streamed, ch>=8 A=corr resident
    for (int ch = 0; ch < 16; ch++) {
        const int s = ch & 1;
        if (ch < 15) {
            if (ch + 1 < 8) issueAbase(s ^ 1, ch + 1);
            issueB(s ^ 1, ch + 1, Wtf); cp_commit(); cp_wait<1>();
        } else { cp_wait<0>(); }
        __syncthreads();
        if (ch < 8) {
            computeA(s);
        } else {
            const float* bs = Bs + s * 128 * LDB2;
#pragma unroll
            for (int ks = 0; ks < 2; ks++) {
                const int k = (ch - 8) * 16 + ks * 8 + lc;
                uint32_t a[2][4];
#pragma unroll
                for (int mi = 0; mi < 2; mi++) {
                    const int row = warpM * 32 + mi * 16 + lr;
                    a[mi][0] = __float_as_uint(corr[row * LDE + k]);
                    a[mi][1] = __float_as_uint(corr[(row + 8) * LDE + k]);
                    a[mi][2] = __float_as_uint(corr[row * LDE + k + 4]);
                    a[mi][3] = __float_as_uint(corr[(row + 8) * LDE + k + 4]);
                }
#pragma unroll
                for (int ni = 0; ni < 8; ni++) {
                    const int n = warpN * 64 + ni * 8 + lr;
                    const float2 bp2 = *(const float2*)&bs[n * LDB2 + ks * 8 + 2 * lc];
#pragma unroll
                    for (int mi = 0; mi < 2; mi++)
                        mma_tf32(c[mi][ni], a[mi], __float_as_uint(bp2.x), __float_as_uint(bp2.y));
                }
            }
        }
        __syncthreads();
    }

    // ---- fuse epilogue: relu(v + bf) -> out
#pragma unroll
    for (int mi = 0; mi < 2; mi++)
#pragma unroll
        for (int half = 0; half < 2; half++) {
            const int row = m0 + warpM * 32 + mi * 16 + lr + half * 8;
            if (row >= M) continue;
#pragma unroll
            for (int ni = 0; ni < 8; ni++) {
                const int col = warpN * 64 + ni * 8 + lc * 2;
                *(float2*)(out + (size_t)row * HID + col) =
                    make_float2(fmaxf(c[mi][ni][half * 2 + 0] + sbf[col + 0], 0.f),
                                fmaxf(c[mi][ni][half * 2 + 1] + sbf[col + 1], 0.f));
            }
        }
}

// ---------------- edge-index dtype sniff ----------------------------------------
__global__ void detect_idx(const unsigned int* __restrict__ p, int E2) {
    __shared__ int any;
    if (threadIdx.x == 0) any = 0;
    __syncthreads();
    int nsamp = E2 / 2; if (nsamp > 2048) nsamp = 2048;
    for (int i = threadIdx.x; i < nsamp; i += blockDim.x)
        if (p[2 * i + 1] != 0u) atomicOr(&any, 1);
    __syncthreads();
    if (threadIdx.x == 0) g_is64 = any ? 0 : 1;
}

__device__ __forceinline__ int edge_val(const void* ei, size_t idx) {
    return g_is64 ? (int)((const long long*)ei)[idx] : ((const int*)ei)[idx];
}

// ---------------- degree / CSR ---------------------------------------------------
__global__ void count_deg(const void* __restrict__ ei, int E) {
    int e = blockIdx.x * blockDim.x + threadIdx.x;
    if (e >= E) return;
    int d = edge_val(ei, (size_t)E + e);
    atomicAdd(&g_deg[d], 1);
}
__global__ void scan1(int n) {
    __shared__ int sh[512];
    int i = blockIdx.x * 512 + threadIdx.x;
    int v = (i < n) ? g_deg[i] : 0;
    if (i < n) g_dis[i] = rsqrtf((float)(v + 1));
    sh[threadIdx.x] = v;
    __syncthreads();
    for (int off = 256; off > 0; off >>= 1) {
        if (threadIdx.x < off) sh[threadIdx.x] += sh[threadIdx.x + off];
        __syncthreads();
    }
    if (threadIdx.x == 0) g_bsum[blockIdx.x] = sh[0];
}
__global__ void scan2(int nb) {
    __shared__ int sh[1024];
    int tid = threadIdx.x;
    int v = (tid < nb) ? g_bsum[tid] : 0;
    sh[tid] = v;
    __syncthreads();
    for (int off = 1; off < 1024; off <<= 1) {
        int t = (tid >= off) ? sh[tid - off] : 0;
        __syncthreads();
        sh[tid] += t;
        __syncthreads();
    }
    if (tid < nb) g_bsum[tid] = sh[tid] - v;
}
__global__ void scan3(int n) {
    __shared__ int sh[512];
    int tid = threadIdx.x;
    int i = blockIdx.x * 512 + tid;
    int v = (i < n) ? g_deg[i] : 0;
    sh[tid] = v;
    __syncthreads();
    for (int off = 1; off < 512; off <<= 1) {
        int t = (tid >= off) ? sh[tid - off] : 0;
        __syncthreads();
        sh[tid] += t;
        __syncthreads();
    }
    if (i < n) {
        int rs = g_bsum[blockIdx.x] + sh[tid] - v;
        g_rowstart[i] = rs;
        g_cursor[i]   = rs;
    }
}
__global__ void fill_csr(const void* __restrict__ ei, int E) {
    int e = blockIdx.x * blockDim.x + threadIdx.x;
    if (e >= E) return;
    int s = edge_val(ei, e);
    int d = edge_val(ei, (size_t)E + e);
    int pos = atomicAdd(&g_cursor[d], 1);
    g_csr[pos] = s;
}

// ---------------- aggregation: warp per node, gather-sum -------------------------
__global__ void aggregate(const float* __restrict__ b_gcn, int n) {
    int gw   = (blockIdx.x * blockDim.x + threadIdx.x) >> 5;
    int lane = threadIdx.x & 31;
    if (gw >= n) return;
    const int node = gw;
    const float4* __restrict__ xg4 = (const float4*)g_xg;

    float4 selfv = xg4[(size_t)node * 32 + lane];
    float  dn    = g_dis[node];
    int    s0    = g_rowstart[node];
    int    cnt   = g_deg[node];

    float4 acc = make_float4(0.f, 0.f, 0.f, 0.f);
    int e = s0, eend = s0 + cnt;
    for (; e + 1 < eend; e += 2) {
        int s1 = g_csr[e], s2 = g_csr[e + 1];
        float w1 = g_dis[s1], w2 = g_dis[s2];
        float4 v1 = xg4[(size_t)s1 * 32 + lane];
        float4 v2 = xg4[(size_t)s2 * 32 + lane];
        acc.x += v1.x * w1 + v2.x * w2;
        acc.y += v1.y * w1 + v2.y * w2;
        acc.z += v1.z * w1 + v2.z * w2;
        acc.w += v1.w * w1 + v2.w * w2;
    }
    if (e < eend) {
        int s1 = g_csr[e];
        float w1 = g_dis[s1];
        float4 v1 = xg4[(size_t)s1 * 32 + lane];
        acc.x += v1.x * w1; acc.y += v1.y * w1;
        acc.z += v1.z * w1; acc.w += v1.w * w1;
    }
    const float sw = dn * dn;
    float4 b = ((const float4*)b_gcn)[lane];
    float4 o;
    o.x = fmaxf(acc.x * dn + selfv.x * sw + b.x, 0.f);
    o.y = fmaxf(acc.y * dn + selfv.y * sw + b.y, 0.f);
    o.z = fmaxf(acc.z * dn + selfv.z * sw + b.z, 0.f);
    o.w = fmaxf(acc.w * dn + selfv.w * sw + b.w, 0.f);
    ((float4*)g_diffused)[(size_t)node * 32 + lane] = o;
}

// ---------------- launcher --------------------------------------------------------
extern "C" void kernel_launch(void* const* d_in, const int* in_sizes, int n_in,
                              void* d_out, int out_size)
{
    const float* base   = (const float*)d_in[0];
    const float* ev     = (const float*)d_in[1];
    const void*  ei     = d_in[2];
    const float* W_proj = (const float*)d_in[3];
    const float* b_proj = (const float*)d_in[4];
    const float* W_gcn  = (const float*)d_in[5];
    const float* b_gcn  = (const float*)d_in[6];
    const float* W_gate = (const float*)d_in[7];
    const float* b_gate = (const float*)d_in[8];
    const float* W_fuse = (const float*)d_in[9];
    const float* b_fuse = (const float*)d_in[10];

    const int N = in_sizes[0] / HID;
    const int E = in_sizes[2] / 2;

    float *p_xg, *p_diff, *p_wtp, *p_wtg, *p_wtga, *p_wtf;
    int *p_deg;
    cudaGetSymbolAddress((void**)&p_xg,   g_xg);
    cudaGetSymbolAddress((void**)&p_diff, g_diffused);
    cudaGetSymbolAddress((void**)&p_wtp,  g_wt_proj);
    cudaGetSymbolAddress((void**)&p_wtg,  g_wt_gcn);
    cudaGetSymbolAddress((void**)&p_wtga, g_wt_gate);
    cudaGetSymbolAddress((void**)&p_wtf,  g_wt_fuse);
    cudaGetSymbolAddress((void**)&p_deg,  g_deg);

    cudaFuncSetAttribute(k_proj_gcn,  cudaFuncAttributeMaxDynamicSharedMemorySize, SMEM_BYTES);
    cudaFuncSetAttribute(k_gate_fuse, cudaFuncAttributeMaxDynamicSharedMemorySize, SMEM_BYTES);

    const int gT = (N + 127) / 128;
    const int gE = (E + 255) / 256;
    const int nb = (N + 511) / 512;

    detect_idx<<<1, 256>>>((const unsigned int*)ei, 2 * E);
    cudaMemsetAsync(p_deg, 0, (size_t)N * sizeof(int));
    wprep<<<88, 256>>>(W_proj, W_gcn, W_gate, W_fuse, p_wtp, p_wtg, p_wtga, p_wtf);
    count_deg<<<gE, 256>>>(ei, E);

    // fused proj+gcn (ncu capture slot)
    k_proj_gcn<<<gT, 256, SMEM_BYTES>>>(ev, p_wtp, b_proj, p_wtg, p_xg, N);

    scan1<<<nb, 512>>>(N);
    scan2<<<1, 1024>>>(nb);
    scan3<<<nb, 512>>>(N);
    fill_csr<<<gE, 256>>>(ei, E);

    aggregate<<<(N * 32 + 255) / 256, 256>>>(b_gcn, N);

    k_gate_fuse<<<gT, 256, SMEM_BYTES>>>(base, p_diff, p_wtga, b_gate,
                                         p_wtf, b_fuse, (float*)d_out, N);
}

// round 7
// speedup vs baseline: 4.1187x; 1.0949x over previous
#include <cuda_runtime.h>
#include <cuda_fp16.h>
#include <cstdint>

#define NMAX 100000
#define EMAX 1600000
#define HID 128

// ---------------- scratch (device globals; no allocations allowed) ----------
__device__ __half2 g_xgh[(size_t)NMAX * 64];     // xg in fp16 (aggregate input)
__device__ float g_diffused[(size_t)NMAX * HID];
__device__ int   g_deg[NMAX];
__device__ float g_dis[NMAX];
__device__ int   g_rowstart[NMAX];
__device__ int   g_cursor[NMAX];
__device__ int   g_csr[EMAX];
__device__ int   g_bsum[1024];
__device__ int   g_is64;
// transposed + k-permuted + tf32-pre-rounded weights [128 n][K k]
__device__ float g_wt_proj[128 * 64];
__device__ float g_wt_gcn [128 * 128];
__device__ float g_wt_gate[128 * 256];
__device__ float g_wt_fuse[128 * 256];

// ---------------- PTX helpers --------------------------------------------------
__device__ __forceinline__ uint32_t smem_u32(const void* p) {
    uint32_t a;
    asm("{ .reg .u64 t; cvta.to.shared.u64 t, %1; cvt.u32.u64 %0, t; }" : "=r"(a) : "l"(p));
    return a;
}
__device__ __forceinline__ void cp16(uint32_t dst, const void* src) {
    asm volatile("cp.async.cg.shared.global [%0], [%1], 16;" :: "r"(dst), "l"(src));
}
__device__ __forceinline__ void cp_commit() {
    asm volatile("cp.async.commit_group;" ::: "memory");
}
template<int N>
__device__ __forceinline__ void cp_wait() {
    asm volatile("cp.async.wait_group %0;" :: "n"(N) : "memory");
}
__device__ __forceinline__ uint32_t to_tf32(float f) {
    uint32_t u;
    asm("cvt.rna.tf32.f32 %0, %1;" : "=r"(u) : "f"(f));
    return u;
}
__device__ __forceinline__ void mma_tf32(float* c, const uint32_t* a, uint32_t b0, uint32_t b1) {
    asm volatile(
        "mma.sync.aligned.m16n8k8.row.col.f32.tf32.tf32.f32 "
        "{%0,%1,%2,%3}, {%4,%5,%6,%7}, {%8,%9}, {%0,%1,%2,%3};"
        : "+f"(c[0]), "+f"(c[1]), "+f"(c[2]), "+f"(c[3])
        : "r"(a[0]), "r"(a[1]), "r"(a[2]), "r"(a[3]), "r"(b0), "r"(b1));
}

// tile geometry shared by both fused kernels
#define LDA  20
#define LDB2 24
#define LDE  132
#define SMEM_FLOATS (128 * LDE + 2 * 128 * LDA + 2 * 128 * LDB2 + 256)
#define SMEM_BYTES  (SMEM_FLOATS * 4)

// ---------------- weight prep: Wt[n][perm(k)] = tf32_rna(W[k][n]) ---------------
__device__ __forceinline__ int pos16(int q) {
    return (q < 4) ? 2 * q
         : (q < 8) ? 2 * (q - 4) + 1
         : (q < 12) ? 8 + 2 * (q - 8)
         : 8 + 2 * (q - 12) + 1;
}
__global__ void wprep(const float* __restrict__ W0, const float* __restrict__ W1,
                      const float* __restrict__ W2, const float* __restrict__ W3,
                      float* __restrict__ T0, float* __restrict__ T1,
                      float* __restrict__ T2, float* __restrict__ T3)
{
    __shared__ float s[32][33];
    int b = blockIdx.x;
    const float* W; float* T; int K;
    if (b < 8)       { W = W0; T = T0; K = 64;  }
    else if (b < 24) { W = W1; T = T1; K = 128; b -= 8;  }
    else if (b < 56) { W = W2; T = T2; K = 256; b -= 24; }
    else             { W = W3; T = T3; K = 256; b -= 56; }
    const int k0 = (b >> 2) * 32, n0 = (b & 3) * 32;
    const int tx = threadIdx.x & 31, ty = threadIdx.x >> 5;
#pragma unroll
    for (int i = 0; i < 4; i++)
        s[ty + i * 8][tx] = W[(size_t)(k0 + ty + i * 8) * HID + n0 + tx];
    __syncthreads();
    const int k = k0 + tx;
    const int q = k & 15;
    const int col = (k - q) + pos16(q);
#pragma unroll
    for (int i = 0; i < 4; i++) {
        const int n = n0 + ty + i * 8;
        T[(size_t)n * K + col] = __uint_as_float(to_tf32(s[tx][ty + i * 8]));
    }
}

// ================================================================================
// Fused kernel 1: ef = relu(ev @ Wp + bp) [smem-resident] ; xg = ef @ Wgcn -> fp16
// ================================================================================
__global__ void __launch_bounds__(256, 2)
k_proj_gcn(const float* __restrict__ ev, const float* __restrict__ Wtp,
           const float* __restrict__ bp, const float* __restrict__ Wtg,
           __half2* __restrict__ xgh, int M)
{
    extern __shared__ float dsm[];
    float* ef = dsm;
    float* As = dsm + 128 * LDE;
    float* Bs = As + 2 * 128 * LDA;
    float* sb = Bs + 2 * 128 * LDB2;

    const int tid   = threadIdx.x;
    const int wid   = tid >> 5, lane = tid & 31;
    const int warpM = wid & 3,  warpN = wid >> 2;
    const int lr    = lane >> 2, lc = lane & 3;
    const int m0    = blockIdx.x * 128;

    if (tid < 128) sb[tid] = bp[tid];

    const uint32_t as_u[2] = { smem_u32(As), smem_u32(As + 128 * LDA) };
    const uint32_t bs_u[2] = { smem_u32(Bs), smem_u32(Bs + 128 * LDB2) };

    float c[2][8][4];
#pragma unroll
    for (int mi = 0; mi < 2; mi++)
#pragma unroll
        for (int ni = 0; ni < 8; ni++)
#pragma unroll
            for (int j = 0; j < 4; j++) c[mi][ni][j] = 0.f;

    auto issueA1 = [&](int s, int ch) {
        const int kc = ch * 16;
#pragma unroll
        for (int i = 0; i < 2; i++) {
            const int idx = tid + i * 256;
            const int r = idx >> 2, q = idx & 3;
            int gr = m0 + r; if (gr > M - 1) gr = M - 1;
            cp16(as_u[s] + (uint32_t)(r * LDA + q * 4) * 4,
                 ev + (size_t)gr * 64 + kc + q * 4);
        }
    };
    auto issueB = [&](int s, int ch, const float* Wt, int KT) {
        const int kc = ch * 16;
#pragma unroll
        for (int i = 0; i < 2; i++) {
            const int idx = tid + i * 256;
            const int n = idx >> 2, q = idx & 3;
            cp16(bs_u[s] + (uint32_t)(n * LDB2 + q * 4) * 4,
                 Wt + (size_t)n * KT + kc + q * 4);
        }
    };
    auto compute = [&](int s) {
        const float* as = As + s * 128 * LDA;
        const float* bs = Bs + s * 128 * LDB2;
#pragma unroll
        for (int ks = 0; ks < 2; ks++) {
            const int k = ks * 8 + lc;
            uint32_t a[2][4];
#pragma unroll
            for (int mi = 0; mi < 2; mi++) {
                const int row = warpM * 32 + mi * 16 + lr;
                a[mi][0] = to_tf32(as[row * LDA + k]);
                a[mi][1] = to_tf32(as[(row + 8) * LDA + k]);
                a[mi][2] = to_tf32(as[row * LDA + k + 4]);
                a[mi][3] = to_tf32(as[(row + 8) * LDA + k + 4]);
            }
#pragma unroll
            for (int ni = 0; ni < 8; ni++) {
                const int n = warpN * 64 + ni * 8 + lr;
                const float2 bp2 = *(const float2*)&bs[n * LDB2 + ks * 8 + 2 * lc];
#pragma unroll
                for (int mi = 0; mi < 2; mi++)
                    mma_tf32(c[mi][ni], a[mi], __float_as_uint(bp2.x), __float_as_uint(bp2.y));
            }
        }
    };

    // ---- phase 1: K=64
    issueA1(0, 0); issueB(0, 0, Wtp, 64); cp_commit();
    for (int ch = 0; ch < 4; ch++) {
        const int s = ch & 1;
        if (ch < 3) { issueA1(s ^ 1, ch + 1); issueB(s ^ 1, ch + 1, Wtp, 64); cp_commit(); cp_wait<1>(); }
        else        { cp_wait<0>(); }
        __syncthreads();
        compute(s);
        __syncthreads();
    }

    issueB(0, 0, Wtg, 128); cp_commit();

    // ---- epilogue 1: relu(v+b) -> tf32 bits into ef smem
#pragma unroll
    for (int mi = 0; mi < 2; mi++)
#pragma unroll
        for (int half = 0; half < 2; half++) {
            const int row = warpM * 32 + mi * 16 + lr + half * 8;
#pragma unroll
            for (int ni = 0; ni < 8; ni++) {
                const int col = warpN * 64 + ni * 8 + lc * 2;
                const float v0 = fmaxf(c[mi][ni][half * 2 + 0] + sb[col + 0], 0.f);
                const float v1 = fmaxf(c[mi][ni][half * 2 + 1] + sb[col + 1], 0.f);
                *(float2*)&ef[row * LDE + col] =
                    make_float2(__uint_as_float(to_tf32(v0)), __uint_as_float(to_tf32(v1)));
            }
        }
    __syncthreads();

#pragma unroll
    for (int mi = 0; mi < 2; mi++)
#pragma unroll
        for (int ni = 0; ni < 8; ni++)
#pragma unroll
            for (int j = 0; j < 4; j++) c[mi][ni][j] = 0.f;

    // ---- phase 2: xg = ef @ Wgcn, A resident
    for (int ch = 0; ch < 8; ch++) {
        const int s = ch & 1;
        if (ch < 7) { issueB(s ^ 1, ch + 1, Wtg, 128); cp_commit(); cp_wait<1>(); }
        else        { cp_wait<0>(); }
        __syncthreads();
        const float* bs = Bs + s * 128 * LDB2;
#pragma unroll
        for (int ks = 0; ks < 2; ks++) {
            const int k = ch * 16 + ks * 8 + lc;
            uint32_t a[2][4];
#pragma unroll
            for (int mi = 0; mi < 2; mi++) {
                const int row = warpM * 32 + mi * 16 + lr;
                a[mi][0] = __float_as_uint(ef[row * LDE + k]);
                a[mi][1] = __float_as_uint(ef[(row + 8) * LDE + k]);
                a[mi][2] = __float_as_uint(ef[row * LDE + k + 4]);
                a[mi][3] = __float_as_uint(ef[(row + 8) * LDE + k + 4]);
            }
#pragma unroll
            for (int ni = 0; ni < 8; ni++) {
                const int n = warpN * 64 + ni * 8 + lr;
                const float2 bp2 = *(const float2*)&bs[n * LDB2 + ks * 8 + 2 * lc];
#pragma unroll
                for (int mi = 0; mi < 2; mi++)
                    mma_tf32(c[mi][ni], a[mi], __float_as_uint(bp2.x), __float_as_uint(bp2.y));
            }
        }
        __syncthreads();
    }

    // ---- epilogue 2: xg -> fp16
#pragma unroll
    for (int mi = 0; mi < 2; mi++)
#pragma unroll
        for (int half = 0; half < 2; half++) {
            const int row = m0 + warpM * 32 + mi * 16 + lr + half * 8;
            if (row >= M) continue;
#pragma unroll
            for (int ni = 0; ni < 8; ni++) {
                const int col = warpN * 64 + ni * 8 + lc * 2;
                xgh[(size_t)row * 64 + (col >> 1)] =
                    __floats2half2_rn(c[mi][ni][half * 2 + 0], c[mi][ni][half * 2 + 1]);
            }
        }
}

// ================================================================================
// Fused kernel 2: gate/corrected/fuse  (unchanged from R6)
// ================================================================================
__global__ void __launch_bounds__(256, 2)
k_gate_fuse(const float* __restrict__ base, const float* __restrict__ diff,
            const float* __restrict__ Wtg, const float* __restrict__ bg,
            const float* __restrict__ Wtf, const float* __restrict__ bf,
            float* __restrict__ out, int M)
{
    extern __shared__ float dsm[];
    float* corr = dsm;
    float* As   = dsm + 128 * LDE;
    float* Bs   = As + 2 * 128 * LDA;
    float* sbg  = Bs + 2 * 128 * LDB2;
    float* sbf  = sbg + 128;

    const int tid   = threadIdx.x;
    const int wid   = tid >> 5, lane = tid & 31;
    const int warpM = wid & 3,  warpN = wid >> 2;
    const int lr    = lane >> 2, lc = lane & 3;
    const int m0    = blockIdx.x * 128;

    if (tid < 128) { sbg[tid] = bg[tid]; sbf[tid] = bf[tid]; }

    const uint32_t as_u[2] = { smem_u32(As), smem_u32(As + 128 * LDA) };
    const uint32_t bs_u[2] = { smem_u32(Bs), smem_u32(Bs + 128 * LDB2) };

    float c[2][8][4];
#pragma unroll
    for (int mi = 0; mi < 2; mi++)
#pragma unroll
        for (int ni = 0; ni < 8; ni++)
#pragma unroll
            for (int j = 0; j < 4; j++) c[mi][ni][j] = 0.f;

    auto issueA = [&](int s, int ch) {
        const float* Ap = (ch < 8) ? base : diff;
        const int kc = (ch < 8) ? ch * 16 : (ch - 8) * 16;
#pragma unroll
        for (int i = 0; i < 2; i++) {
            const int idx = tid + i * 256;
            const int r = idx >> 2, q = idx & 3;
            int gr = m0 + r; if (gr > M - 1) gr = M - 1;
            cp16(as_u[s] + (uint32_t)(r * LDA + q * 4) * 4,
                 Ap + (size_t)gr * HID + kc + q * 4);
        }
    };
    auto issueAbase = [&](int s, int ch) {
        const int kc = ch * 16;
#pragma unroll
        for (int i = 0; i < 2; i++) {
            const int idx = tid + i * 256;
            const int r = idx >> 2, q = idx & 3;
            int gr = m0 + r; if (gr > M - 1) gr = M - 1;
            cp16(as_u[s] + (uint32_t)(r * LDA + q * 4) * 4,
                 base + (size_t)gr * HID + kc + q * 4);
        }
    };
    auto issueB = [&](int s, int ch, const float* Wt) {
        const int kc = ch * 16;
#pragma unroll
        for (int i = 0; i < 2; i++) {
            const int idx = tid + i * 256;
            const int n = idx >> 2, q = idx & 3;
            cp16(bs_u[s] + (uint32_t)(n * LDB2 + q * 4) * 4,
                 Wt + (size_t)n * 256 + kc + q * 4);
        }
    };
    auto computeA = [&](int s) {
        const float* as = As + s * 128 * LDA;
        const float* bs = Bs + s * 128 * LDB2;
#pragma unroll
        for (int ks = 0; ks < 2; ks++) {
            const int k = ks * 8 + lc;
            uint32_t a[2][4];
#pragma unroll
            for (int mi = 0; mi < 2; mi++) {
                const int row = warpM * 32 + mi * 16 + lr;
                a[mi][0] = to_tf32(as[row * LDA + k]);
                a[mi][1] = to_tf32(as[(row + 8) * LDA + k]);
                a[mi][2] = to_tf32(as[row * LDA + k + 4]);
                a[mi][3] = to_tf32(as[(row + 8) * LDA + k + 4]);
            }
#pragma unroll
            for (int ni = 0; ni < 8; ni++) {
                const int n = warpN * 64 + ni * 8 + lr;
                const float2 bp2 = *(const float2*)&bs[n * LDB2 + ks * 8 + 2 * lc];
#pragma unroll
                for (int mi = 0; mi < 2; mi++)
                    mma_tf32(c[mi][ni], a[mi], __float_as_uint(bp2.x), __float_as_uint(bp2.y));
            }
        }
    };

    // ---- phase A: gate GEMM, K=256
    issueA(0, 0); issueB(0, 0, Wtg); cp_commit();
    for (int ch = 0; ch < 16; ch++) {
        const int s = ch & 1;
        if (ch < 15) { issueA(s ^ 1, ch + 1); issueB(s ^ 1, ch + 1, Wtg); cp_commit(); cp_wait<1>(); }
        else         { cp_wait<0>(); }
        __syncthreads();
        computeA(s);
        __syncthreads();
    }

    issueAbase(0, 0); issueB(0, 0, Wtf); cp_commit();

    // ---- gate epilogue: corrected tile -> smem (tf32 bits)
#pragma unroll
    for (int mi = 0; mi < 2; mi++)
#pragma unroll
        for (int half = 0; half < 2; half++) {
            const int lrow = warpM * 32 + mi * 16 + lr + half * 8;
            const int row  = m0 + lrow;
            if (row >= M) continue;
#pragma unroll
            for (int ni = 0; ni < 8; ni++) {
                const int col = warpN * 64 + ni * 8 + lc * 2;
                const float2 a0 = *(const float2*)(base + (size_t)row * HID + col);
                const float2 a1 = *(const float2*)(diff + (size_t)row * HID + col);
                const float g0 = 1.f / (1.f + __expf(-(c[mi][ni][half * 2 + 0] + sbg[col + 0])));
                const float g1 = 1.f / (1.f + __expf(-(c[mi][ni][half * 2 + 1] + sbg[col + 1])));
                const float v0 = fmaf(a1.x - a0.x, g0, a0.x);
                const float v1 = fmaf(a1.y - a0.y, g1, a0.y);
                *(float2*)&corr[lrow * LDE + col] =
                    make_float2(__uint_as_float(to_tf32(v0)), __uint_as_float(to_tf32(v1)));
            }
        }
    __syncthreads();

#pragma unroll
    for (int mi = 0; mi < 2; mi++)
#pragma unroll
        for (int ni = 0; ni < 8; ni++)
#pragma unroll
            for (int j = 0; j < 4; j++) c[mi][ni][j] = 0.f;

    // ---- phase B: fuse GEMM
    for (int ch = 0; ch < 16; ch++) {
        const int s = ch & 1;
        if (ch < 15) {
            if (ch + 1 < 8) issueAbase(s ^ 1, ch + 1);
            issueB(s ^ 1, ch + 1, Wtf); cp_commit(); cp_wait<1>();
        } else { cp_wait<0>(); }
        __syncthreads();
        if (ch < 8) {
            computeA(s);
        } else {
            const float* bs = Bs + s * 128 * LDB2;
#pragma unroll
            for (int ks = 0; ks < 2; ks++) {
                const int k = (ch - 8) * 16 + ks * 8 + lc;
                uint32_t a[2][4];
#pragma unroll
                for (int mi = 0; mi < 2; mi++) {
                    const int row = warpM * 32 + mi * 16 + lr;
                    a[mi][0] = __float_as_uint(corr[row * LDE + k]);
                    a[mi][1] = __float_as_uint(corr[(row + 8) * LDE + k]);
                    a[mi][2] = __float_as_uint(corr[row * LDE + k + 4]);
                    a[mi][3] = __float_as_uint(corr[(row + 8) * LDE + k + 4]);
                }
#pragma unroll
                for (int ni = 0; ni < 8; ni++) {
                    const int n = warpN * 64 + ni * 8 + lr;
                    const float2 bp2 = *(const float2*)&bs[n * LDB2 + ks * 8 + 2 * lc];
#pragma unroll
                    for (int mi = 0; mi < 2; mi++)
                        mma_tf32(c[mi][ni], a[mi], __float_as_uint(bp2.x), __float_as_uint(bp2.y));
                }
            }
        }
        __syncthreads();
    }

    // ---- fuse epilogue
#pragma unroll
    for (int mi = 0; mi < 2; mi++)
#pragma unroll
        for (int half = 0; half < 2; half++) {
            const int row = m0 + warpM * 32 + mi * 16 + lr + half * 8;
            if (row >= M) continue;
#pragma unroll
            for (int ni = 0; ni < 8; ni++) {
                const int col = warpN * 64 + ni * 8 + lc * 2;
                *(float2*)(out + (size_t)row * HID + col) =
                    make_float2(fmaxf(c[mi][ni][half * 2 + 0] + sbf[col + 0], 0.f),
                                fmaxf(c[mi][ni][half * 2 + 1] + sbf[col + 1], 0.f));
            }
        }
}

// ---------------- edge-index dtype sniff ----------------------------------------
__global__ void detect_idx(const unsigned int* __restrict__ p, int E2) {
    __shared__ int any;
    if (threadIdx.x == 0) any = 0;
    __syncthreads();
    int nsamp = E2 / 2; if (nsamp > 2048) nsamp = 2048;
    for (int i = threadIdx.x; i < nsamp; i += blockDim.x)
        if (p[2 * i + 1] != 0u) atomicOr(&any, 1);
    __syncthreads();
    if (threadIdx.x == 0) g_is64 = any ? 0 : 1;
}

__device__ __forceinline__ int edge_val(const void* ei, size_t idx) {
    return g_is64 ? (int)((const long long*)ei)[idx] : ((const int*)ei)[idx];
}

// ---------------- degree / CSR ---------------------------------------------------
__global__ void count_deg(const void* __restrict__ ei, int E) {
    int e = blockIdx.x * blockDim.x + threadIdx.x;
    if (e >= E) return;
    int d = edge_val(ei, (size_t)E + e);
    atomicAdd(&g_deg[d], 1);
}
__global__ void scan1(int n) {
    __shared__ int sh[512];
    int i = blockIdx.x * 512 + threadIdx.x;
    int v = (i < n) ? g_deg[i] : 0;
    if (i < n) g_dis[i] = rsqrtf((float)(v + 1));
    sh[threadIdx.x] = v;
    __syncthreads();
    for (int off = 256; off > 0; off >>= 1) {
        if (threadIdx.x < off) sh[threadIdx.x] += sh[threadIdx.x + off];
        __syncthreads();
    }
    if (threadIdx.x == 0) g_bsum[blockIdx.x] = sh[0];
}
__global__ void scan2(int nb) {
    __shared__ int sh[1024];
    int tid = threadIdx.x;
    int v = (tid < nb) ? g_bsum[tid] : 0;
    sh[tid] = v;
    __syncthreads();
    for (int off = 1; off < 1024; off <<= 1) {
        int t = (tid >= off) ? sh[tid - off] : 0;
        __syncthreads();
        sh[tid] += t;
        __syncthreads();
    }
    if (tid < nb) g_bsum[tid] = sh[tid] - v;
}
__global__ void scan3(int n) {
    __shared__ int sh[512];
    int tid = threadIdx.x;
    int i = blockIdx.x * 512 + tid;
    int v = (i < n) ? g_deg[i] : 0;
    sh[tid] = v;
    __syncthreads();
    for (int off = 1; off < 512; off <<= 1) {
        int t = (tid >= off) ? sh[tid - off] : 0;
        __syncthreads();
        sh[tid] += t;
        __syncthreads();
    }
    if (i < n) {
        int rs = g_bsum[blockIdx.x] + sh[tid] - v;
        g_rowstart[i] = rs;
        g_cursor[i]   = rs;
    }
}
__global__ void fill_csr(const void* __restrict__ ei, int E) {
    int e = blockIdx.x * blockDim.x + threadIdx.x;
    if (e >= E) return;
    int s = edge_val(ei, e);
    int d = edge_val(ei, (size_t)E + e);
    int pos = atomicAdd(&g_cursor[d], 1);
    g_csr[pos] = s;
}

// ---------------- aggregation: warp per node, fp16 gather-sum --------------------
__device__ __forceinline__ float4 h4f(uint2 v) {
    const float2 f0 = __half22float2(*(const __half2*)&v.x);
    const float2 f1 = __half22float2(*(const __half2*)&v.y);
    return make_float4(f0.x, f0.y, f1.x, f1.y);
}
__global__ void aggregate(const float* __restrict__ b_gcn, int n) {
    int gw   = (blockIdx.x * blockDim.x + threadIdx.x) >> 5;
    int lane = threadIdx.x & 31;
    if (gw >= n) return;
    const int node = gw;
    const uint2* __restrict__ xg2 = (const uint2*)g_xgh;  // 32 uint2 (=256B) per row

    const float4 selfv = h4f(xg2[(size_t)node * 32 + lane]);
    const float  dn    = g_dis[node];
    const int    s0    = g_rowstart[node];
    const int    cnt   = g_deg[node];

    float4 acc = make_float4(0.f, 0.f, 0.f, 0.f);
    int e = s0, eend = s0 + cnt;
    for (; e + 1 < eend; e += 2) {
        const int s1 = g_csr[e], s2 = g_csr[e + 1];
        const float w1 = g_dis[s1], w2 = g_dis[s2];
        const float4 v1 = h4f(xg2[(size_t)s1 * 32 + lane]);
        const float4 v2 = h4f(xg2[(size_t)s2 * 32 + lane]);
        acc.x += v1.x * w1 + v2.x * w2;
        acc.y += v1.y * w1 + v2.y * w2;
        acc.z += v1.z * w1 + v2.z * w2;
        acc.w += v1.w * w1 + v2.w * w2;
    }
    if (e < eend) {
        const int s1 = g_csr[e];
        const float w1 = g_dis[s1];
        const float4 v1 = h4f(xg2[(size_t)s1 * 32 + lane]);
        acc.x += v1.x * w1; acc.y += v1.y * w1;
        acc.z += v1.z * w1; acc.w += v1.w * w1;
    }
    const float sw = dn * dn;
    const float4 b = ((const float4*)b_gcn)[lane];
    float4 o;
    o.x = fmaxf(acc.x * dn + selfv.x * sw + b.x, 0.f);
    o.y = fmaxf(acc.y * dn + selfv.y * sw + b.y, 0.f);
    o.z = fmaxf(acc.z * dn + selfv.z * sw + b.z, 0.f);
    o.w = fmaxf(acc.w * dn + selfv.w * sw + b.w, 0.f);
    ((float4*)g_diffused)[(size_t)node * 32 + lane] = o;
}

// ---------------- launcher --------------------------------------------------------
extern "C" void kernel_launch(void* const* d_in, const int* in_sizes, int n_in,
                              void* d_out, int out_size)
{
    const float* base   = (const float*)d_in[0];
    const float* ev     = (const float*)d_in[1];
    const void*  ei     = d_in[2];
    const float* W_proj = (const float*)d_in[3];
    const float* b_proj = (const float*)d_in[4];
    const float* W_gcn  = (const float*)d_in[5];
    const float* b_gcn  = (const float*)d_in[6];
    const float* W_gate = (const float*)d_in[7];
    const float* b_gate = (const float*)d_in[8];
    const float* W_fuse = (const float*)d_in[9];
    const float* b_fuse = (const float*)d_in[10];

    const int N = in_sizes[0] / HID;
    const int E = in_sizes[2] / 2;

    __half2 *p_xgh;
    float *p_diff, *p_wtp, *p_wtg, *p_wtga, *p_wtf;
    int *p_deg;
    cudaGetSymbolAddress((void**)&p_xgh,  g_xgh);
    cudaGetSymbolAddress((void**)&p_diff, g_diffused);
    cudaGetSymbolAddress((void**)&p_wtp,  g_wt_proj);
    cudaGetSymbolAddress((void**)&p_wtg,  g_wt_gcn);
    cudaGetSymbolAddress((void**)&p_wtga, g_wt_gate);
    cudaGetSymbolAddress((void**)&p_wtf,  g_wt_fuse);
    cudaGetSymbolAddress((void**)&p_deg,  g_deg);

    cudaFuncSetAttribute(k_proj_gcn,  cudaFuncAttributeMaxDynamicSharedMemorySize, SMEM_BYTES);
    cudaFuncSetAttribute(k_gate_fuse, cudaFuncAttributeMaxDynamicSharedMemorySize, SMEM_BYTES);

    const int gT = (N + 127) / 128;
    const int gE = (E + 255) / 256;
    const int nb = (N + 511) / 512;

    // fork a side stream for the CSR chain (capturable fork/join pattern)
    cudaStream_t side;
    cudaEvent_t evFork, evJoin;
    cudaStreamCreateWithFlags(&side, cudaStreamNonBlocking);
    cudaEventCreateWithFlags(&evFork, cudaEventDisableTiming);
    cudaEventCreateWithFlags(&evJoin, cudaEventDisableTiming);

    cudaEventRecord(evFork, 0);
    cudaStreamWaitEvent(side, evFork, 0);

    // --- side stream: CSR build
    detect_idx<<<1, 256, 0, side>>>((const unsigned int*)ei, 2 * E);
    cudaMemsetAsync(p_deg, 0, (size_t)N * sizeof(int), side);
    count_deg<<<gE, 256, 0, side>>>(ei, E);
    scan1<<<nb, 512, 0, side>>>(N);
    scan2<<<1, 1024, 0, side>>>(nb);
    scan3<<<nb, 512, 0, side>>>(N);
    fill_csr<<<gE, 256, 0, side>>>(ei, E);
    cudaEventRecord(evJoin, side);

    // --- main stream: weight prep + fused proj/gcn GEMM (overlaps CSR)
    wprep<<<88, 256>>>(W_proj, W_gcn, W_gate, W_fuse, p_wtp, p_wtg, p_wtga, p_wtf);
    k_proj_gcn<<<gT, 256, SMEM_BYTES>>>(ev, p_wtp, b_proj, p_wtg, p_xgh, N);

    // join: aggregate needs xg (main) + CSR (side)
    cudaStreamWaitEvent(0, evJoin, 0);
    aggregate<<<(N * 32 + 255) / 256, 256>>>(b_gcn, N);

    k_gate_fuse<<<gT, 256, SMEM_BYTES>>>(base, p_diff, p_wtga, b_gate,
                                         p_wtf, b_fuse, (float*)d_out, N);
}

// round 8
// speedup vs baseline: 4.4125x; 1.0713x over previous
#include <cuda_runtime.h>
#include <cuda_fp16.h>
#include <cstdint>

#define NMAX 100000
#define EMAX 1600000
#define HID 128

// ---------------- scratch (device globals; no allocations allowed) ----------
__device__ uint32_t g_xgh  [(size_t)NMAX * 64];   // xg fp16, plain layout (64 words/row)
__device__ uint32_t g_diffh[(size_t)NMAX * 64];   // diffused fp16, k-permuted
__device__ uint32_t g_evh  [(size_t)NMAX * 32];   // ev fp16, k-permuted
__device__ uint32_t g_baseh[(size_t)NMAX * 64];   // base fp16, k-permuted
__device__ int   g_deg[NMAX];
__device__ float g_dis[NMAX];
__device__ int   g_rowstart[NMAX];
__device__ int   g_cursor[NMAX];
__device__ int   g_csr[EMAX];
__device__ int   g_bsum[1024];
__device__ int   g_is64;
// fp16 transposed + k-permuted weights [128 n][K k]
__device__ __half g_wt_proj[128 * 64];
__device__ __half g_wt_gcn [128 * 128];
__device__ __half g_wt_gate[128 * 256];
__device__ __half g_wt_fuse[128 * 256];

// ---------------- PTX helpers --------------------------------------------------
__device__ __forceinline__ uint32_t smem_u32(const void* p) {
    uint32_t a;
    asm("{ .reg .u64 t; cvta.to.shared.u64 t, %1; cvt.u32.u64 %0, t; }" : "=r"(a) : "l"(p));
    return a;
}
__device__ __forceinline__ void cp16(uint32_t dst, const void* src) {
    asm volatile("cp.async.cg.shared.global [%0], [%1], 16;" :: "r"(dst), "l"(src));
}
__device__ __forceinline__ void cp_commit() {
    asm volatile("cp.async.commit_group;" ::: "memory");
}
template<int N>
__device__ __forceinline__ void cp_wait() {
    asm volatile("cp.async.wait_group %0;" :: "n"(N) : "memory");
}
__device__ __forceinline__ void mma_f16(float* c, uint32_t a0, uint32_t a1,
                                        uint32_t a2, uint32_t a3,
                                        uint32_t b0, uint32_t b1) {
    asm volatile(
        "mma.sync.aligned.m16n8k16.row.col.f32.f16.f16.f32 "
        "{%0,%1,%2,%3}, {%4,%5,%6,%7}, {%8,%9}, {%0,%1,%2,%3};"
        : "+f"(c[0]), "+f"(c[1]), "+f"(c[2]), "+f"(c[3])
        : "r"(a0), "r"(a1), "r"(a2), "r"(a3), "r"(b0), "r"(b1));
}

// k-word permutation within each 8-word (16-half) group: pairs (w, w+4) -> (2w', 2w'+1)
__device__ __forceinline__ int perm8(int w) { return (w < 4) ? 2 * w : 2 * (w - 4) + 1; }
__device__ __forceinline__ int permw(int w) { return ((w >> 3) << 3) + perm8(w & 7); }

// smem geometry (uint32 words)
#define LDR 72                         // resident tile stride (128 halves + pad)
#define EF_W   (128 * LDR)             // 9216
#define STG_W  (128 * 8)               // one A or B stage: 1024 words
// k_proj_gcn:  ef | 3 A stages | 3 B stages | bias(128 f)
#define PG_SMEM_W (EF_W + 3 * STG_W + 3 * STG_W + 128)
// k_gate_fuse: corr | baseR | 3 A stages | 3 B stages | 2 biases
#define GF_SMEM_W (2 * EF_W + 3 * STG_W + 3 * STG_W + 256)

// ---------------- weight prep: half Wt[n][permk(k)] = W[k][n] -------------------
__global__ void wprep(const float* __restrict__ W0, const float* __restrict__ W1,
                      const float* __restrict__ W2, const float* __restrict__ W3,
                      __half* __restrict__ T0, __half* __restrict__ T1,
                      __half* __restrict__ T2, __half* __restrict__ T3)
{
    __shared__ float s[32][33];
    int b = blockIdx.x;
    const float* W; __half* T; int K;
    if (b < 8)       { W = W0; T = T0; K = 64;  }
    else if (b < 24) { W = W1; T = T1; K = 128; b -= 8;  }
    else if (b < 56) { W = W2; T = T2; K = 256; b -= 24; }
    else             { W = W3; T = T3; K = 256; b -= 56; }
    const int k0 = (b >> 2) * 32, n0 = (b & 3) * 32;
    const int tx = threadIdx.x & 31, ty = threadIdx.x >> 5;
#pragma unroll
    for (int i = 0; i < 4; i++)
        s[ty + i * 8][tx] = W[(size_t)(k0 + ty + i * 8) * HID + n0 + tx];
    __syncthreads();
    const int k = k0 + tx;
    const int col = ((k >> 4) << 4) + (perm8((k & 15) >> 1) << 1) + (k & 1);
#pragma unroll
    for (int i = 0; i < 4; i++) {
        const int n = n0 + ty + i * 8;
        T[(size_t)n * K + col] = __float2half(s[tx][ty + i * 8]);
    }
}

// ---------------- activation convert: fp32 -> k-permuted fp16 -------------------
template<int WPR>
__global__ void cvt_half(const float2* __restrict__ in, uint32_t* __restrict__ out,
                         int total_words)
{
    int idx = blockIdx.x * blockDim.x + threadIdx.x;
    if (idx >= total_words) return;
    const int row = idx / WPR, w = idx % WPR;
    const float2 v = in[idx];
    const __half2 h = __floats2half2_rn(v.x, v.y);
    out[(size_t)row * WPR + permw(w)] = *(const uint32_t*)&h;
}

// ================================================================================
// Fused kernel 1: ef = relu(evh @ Wp + bp) [fp16 smem-resident]; xg = ef @ Wgcn
// ================================================================================
__global__ void __launch_bounds__(256, 2)
k_proj_gcn(const uint32_t* __restrict__ evh, const __half* __restrict__ Wtp,
           const float* __restrict__ bp, const __half* __restrict__ Wtg,
           uint32_t* __restrict__ xgh, int M)
{
    extern __shared__ uint32_t dsm[];
    uint32_t* ef = dsm;
    uint32_t* As = dsm + EF_W;
    uint32_t* Bs = As + 3 * STG_W;
    float*    sb = (float*)(Bs + 3 * STG_W);

    const int tid   = threadIdx.x;
    const int wid   = tid >> 5, lane = tid & 31;
    const int warpM = wid & 3,  warpN = wid >> 2;
    const int lr    = lane >> 2, lc = lane & 3;
    const int m0    = blockIdx.x * 128;

    if (tid < 128) sb[tid] = bp[tid];

    const uint32_t as_b = smem_u32(As);
    const uint32_t bs_b = smem_u32(Bs);

    float c[2][8][4];
#pragma unroll
    for (int mi = 0; mi < 2; mi++)
#pragma unroll
        for (int ni = 0; ni < 8; ni++)
#pragma unroll
            for (int j = 0; j < 4; j++) c[mi][ni][j] = 0.f;

    // copy one chunk (A: 128x32B, B: 128x32B) -> one cp group
    auto issueA = [&](int st, int ch) {
        const int r = tid >> 1, q = tid & 1;
        int gr = m0 + r; if (gr > M - 1) gr = M - 1;
        cp16(as_b + (uint32_t)(st * STG_W + r * 8 + q * 4) * 4,
             evh + (size_t)gr * 32 + ch * 8 + q * 4);
    };
    auto issueB = [&](int st, int ch, const __half* Wt, int WPRW) {
        const int n = tid >> 1, q = tid & 1;
        cp16(bs_b + (uint32_t)(st * STG_W + n * 8 + q * 4) * 4,
             Wt + (size_t)n * (WPRW * 2) + (ch * 8 + q * 4) * 2);
    };
    auto compute = [&](const uint32_t* Ab, int lda, int wb, const uint32_t* Bb) {
        uint32_t a0[2], a1[2], a2[2], a3[2];
#pragma unroll
        for (int mi = 0; mi < 2; mi++) {
            const int row = warpM * 32 + mi * 16 + lr;
            const uint2 lo = *(const uint2*)(Ab + row * lda + wb + 2 * lc);
            const uint2 hi = *(const uint2*)(Ab + (row + 8) * lda + wb + 2 * lc);
            a0[mi] = lo.x; a1[mi] = hi.x; a2[mi] = lo.y; a3[mi] = hi.y;
        }
#pragma unroll
        for (int ni = 0; ni < 8; ni++) {
            const uint2 bb = *(const uint2*)(Bb + (warpN * 64 + ni * 8 + lr) * 8 + 2 * lc);
#pragma unroll
            for (int mi = 0; mi < 2; mi++)
                mma_f16(c[mi][ni], a0[mi], a1[mi], a2[mi], a3[mi], bb.x, bb.y);
        }
    };

    // ---- phase 1: K=64, 4 chunks, 3-stage pipeline
    issueA(0, 0); issueB(0, 0, Wtp, 32); cp_commit();
    issueA(1, 1); issueB(1, 1, Wtp, 32); cp_commit();
    for (int i = 0; i < 4; i++) {
        if (i < 3) cp_wait<1>(); else cp_wait<0>();
        __syncthreads();
        if (i + 2 < 4) { issueA((i + 2) % 3, i + 2); issueB((i + 2) % 3, i + 2, Wtp, 32); cp_commit(); }
        compute(As + (i % 3) * STG_W, 8, 0, Bs + (i % 3) * STG_W);
    }
    __syncthreads();

    // prefetch phase-2 B chunks 0,1
    issueB(0, 0, Wtg, 64); cp_commit();
    issueB(1, 1, Wtg, 64); cp_commit();

    // ---- epilogue 1: relu(v+b) -> permuted fp16 into ef
#pragma unroll
    for (int mi = 0; mi < 2; mi++)
#pragma unroll
        for (int half = 0; half < 2; half++) {
            const int row = warpM * 32 + mi * 16 + lr + half * 8;
#pragma unroll
            for (int ni = 0; ni < 8; ni++) {
                const int col = warpN * 64 + ni * 8 + lc * 2;
                const float v0 = fmaxf(c[mi][ni][half * 2 + 0] + sb[col + 0], 0.f);
                const float v1 = fmaxf(c[mi][ni][half * 2 + 1] + sb[col + 1], 0.f);
                const __half2 h = __floats2half2_rn(v0, v1);
                ef[row * LDR + permw(col >> 1)] = *(const uint32_t*)&h;
            }
        }

#pragma unroll
    for (int mi = 0; mi < 2; mi++)
#pragma unroll
        for (int ni = 0; ni < 8; ni++)
#pragma unroll
            for (int j = 0; j < 4; j++) c[mi][ni][j] = 0.f;

    // ---- phase 2: xg = ef @ Wgcn, K=128 (8 chunks), A resident
    for (int i = 0; i < 8; i++) {
        if (i < 7) cp_wait<1>(); else cp_wait<0>();
        __syncthreads();
        if (i + 2 < 8) { issueB((i + 2) % 3, i + 2, Wtg, 64); cp_commit(); }
        compute(ef, LDR, i * 8, Bs + (i % 3) * STG_W);
    }

    // ---- epilogue 2: xg fp16 plain layout
#pragma unroll
    for (int mi = 0; mi < 2; mi++)
#pragma unroll
        for (int half = 0; half < 2; half++) {
            const int row = m0 + warpM * 32 + mi * 16 + lr + half * 8;
            if (row >= M) continue;
#pragma unroll
            for (int ni = 0; ni < 8; ni++) {
                const int col = warpN * 64 + ni * 8 + lc * 2;
                const __half2 h = __floats2half2_rn(c[mi][ni][half * 2 + 0],
                                                    c[mi][ni][half * 2 + 1]);
                xgh[(size_t)row * 64 + (col >> 1)] = *(const uint32_t*)&h;
            }
        }
}

// ================================================================================
// Fused kernel 2: gate GEMM -> corrected (smem) -> fuse GEMM
// base tile resident in smem (loaded once); fuse phase has zero A gmem traffic.
// ================================================================================
__global__ void __launch_bounds__(256, 2)
k_gate_fuse(const uint32_t* __restrict__ baseh, const uint32_t* __restrict__ diffh,
            const __half* __restrict__ Wtg, const float* __restrict__ bg,
            const __half* __restrict__ Wtf, const float* __restrict__ bf,
            float* __restrict__ out, int M)
{
    extern __shared__ uint32_t dsm[];
    uint32_t* corr  = dsm;
    uint32_t* baseR = dsm + EF_W;
    uint32_t* As    = baseR + EF_W;
    uint32_t* Bs    = As + 3 * STG_W;
    float*    sbg   = (float*)(Bs + 3 * STG_W);
    float*    sbf   = sbg + 128;

    const int tid   = threadIdx.x;
    const int wid   = tid >> 5, lane = tid & 31;
    const int warpM = wid & 3,  warpN = wid >> 2;
    const int lr    = lane >> 2, lc = lane & 3;
    const int m0    = blockIdx.x * 128;

    if (tid < 128) { sbg[tid] = bg[tid]; sbf[tid] = bf[tid]; }

    const uint32_t br_b = smem_u32(baseR);
    const uint32_t as_b = smem_u32(As);
    const uint32_t bs_b = smem_u32(Bs);

    float c[2][8][4];
#pragma unroll
    for (int mi = 0; mi < 2; mi++)
#pragma unroll
        for (int ni = 0; ni < 8; ni++)
#pragma unroll
            for (int j = 0; j < 4; j++) c[mi][ni][j] = 0.f;

    // gate-phase A copy: ch<8 -> base into resident slice; ch>=8 -> diff into stage
    auto issueA = [&](int ch) {
        const int r = tid >> 1, q = tid & 1;
        int gr = m0 + r; if (gr > M - 1) gr = M - 1;
        if (ch < 8) {
            cp16(br_b + (uint32_t)(r * LDR + ch * 8 + q * 4) * 4,
                 baseh + (size_t)gr * 64 + ch * 8 + q * 4);
        } else {
            cp16(as_b + (uint32_t)(((ch - 8) % 3) * STG_W + r * 8 + q * 4) * 4,
                 diffh + (size_t)gr * 64 + (ch - 8) * 8 + q * 4);
        }
    };
    auto issueB = [&](int ch, const __half* Wt) {
        const int n = tid >> 1, q = tid & 1;
        cp16(bs_b + (uint32_t)((ch % 3) * STG_W + n * 8 + q * 4) * 4,
             Wt + (size_t)n * 256 + (ch * 8 + q * 4) * 2);
    };
    auto compute = [&](const uint32_t* Ab, int lda, int wb, const uint32_t* Bb) {
        uint32_t a0[2], a1[2], a2[2], a3[2];
#pragma unroll
        for (int mi = 0; mi < 2; mi++) {
            const int row = warpM * 32 + mi * 16 + lr;
            const uint2 lo = *(const uint2*)(Ab + row * lda + wb + 2 * lc);
            const uint2 hi = *(const uint2*)(Ab + (row + 8) * lda + wb + 2 * lc);
            a0[mi] = lo.x; a1[mi] = hi.x; a2[mi] = lo.y; a3[mi] = hi.y;
        }
#pragma unroll
        for (int ni = 0; ni < 8; ni++) {
            const uint2 bb = *(const uint2*)(Bb + (warpN * 64 + ni * 8 + lr) * 8 + 2 * lc);
#pragma unroll
            for (int mi = 0; mi < 2; mi++)
                mma_f16(c[mi][ni], a0[mi], a1[mi], a2[mi], a3[mi], bb.x, bb.y);
        }
    };

    // ---- phase A: gate GEMM, K=256 (16 chunks)
    issueA(0); issueB(0, Wtg); cp_commit();
    issueA(1); issueB(1, Wtg); cp_commit();
    for (int i = 0; i < 16; i++) {
        if (i < 15) cp_wait<1>(); else cp_wait<0>();
        __syncthreads();
        if (i + 2 < 16) { issueA(i + 2); issueB(i + 2, Wtg); cp_commit(); }
        if (i < 8) compute(baseR, LDR, i * 8, Bs + (i % 3) * STG_W);
        else       compute(As + ((i - 8) % 3) * STG_W, 8, 0, Bs + (i % 3) * STG_W);
    }
    __syncthreads();

    // prefetch fuse B chunks 0,1
    issueB(0, Wtf); cp_commit();
    issueB(1, Wtf); cp_commit();

    // ---- gate epilogue: corrected -> permuted fp16 in smem
#pragma unroll
    for (int mi = 0; mi < 2; mi++)
#pragma unroll
        for (int half = 0; half < 2; half++) {
            const int lrow = warpM * 32 + mi * 16 + lr + half * 8;
            const int row  = m0 + lrow;
            const size_t rbase = (size_t)(row < M ? row : M - 1) * 64;
#pragma unroll
            for (int ni = 0; ni < 8; ni++) {
                const int col = warpN * 64 + ni * 8 + lc * 2;
                const int pw  = permw(col >> 1);
                const uint32_t ub = baseR[lrow * LDR + pw];
                const uint32_t ud = diffh[rbase + pw];
                const float2 b2 = __half22float2(*(const __half2*)&ub);
                const float2 d2 = __half22float2(*(const __half2*)&ud);
                const float g0 = 1.f / (1.f + __expf(-(c[mi][ni][half * 2 + 0] + sbg[col + 0])));
                const float g1 = 1.f / (1.f + __expf(-(c[mi][ni][half * 2 + 1] + sbg[col + 1])));
                const float v0 = fmaf(d2.x - b2.x, g0, b2.x);
                const float v1 = fmaf(d2.y - b2.y, g1, b2.y);
                const __half2 h = __floats2half2_rn(v0, v1);
                corr[lrow * LDR + pw] = *(const uint32_t*)&h;
            }
        }

#pragma unroll
    for (int mi = 0; mi < 2; mi++)
#pragma unroll
        for (int ni = 0; ni < 8; ni++)
#pragma unroll
            for (int j = 0; j < 4; j++) c[mi][ni][j] = 0.f;

    // ---- phase B: fuse GEMM, K=256; A entirely smem-resident (baseR then corr)
    for (int i = 0; i < 16; i++) {
        if (i < 15) cp_wait<1>(); else cp_wait<0>();
        __syncthreads();
        if (i + 2 < 16) { issueB(i + 2, Wtf); cp_commit(); }
        if (i < 8) compute(baseR, LDR, i * 8, Bs + (i % 3) * STG_W);
        else       compute(corr, LDR, (i - 8) * 8, Bs + (i % 3) * STG_W);
    }

    // ---- fuse epilogue: relu(v + bf) -> out (fp32)
#pragma unroll
    for (int mi = 0; mi < 2; mi++)
#pragma unroll
        for (int half = 0; half < 2; half++) {
            const int row = m0 + warpM * 32 + mi * 16 + lr + half * 8;
            if (row >= M) continue;
#pragma unroll
            for (int ni = 0; ni < 8; ni++) {
                const int col = warpN * 64 + ni * 8 + lc * 2;
                *(float2*)(out + (size_t)row * HID + col) =
                    make_float2(fmaxf(c[mi][ni][half * 2 + 0] + sbf[col + 0], 0.f),
                                fmaxf(c[mi][ni][half * 2 + 1] + sbf[col + 1], 0.f));
            }
        }
}

// ---------------- edge-index dtype sniff ----------------------------------------
__global__ void detect_idx(const unsigned int* __restrict__ p, int E2) {
    __shared__ int any;
    if (threadIdx.x == 0) any = 0;
    __syncthreads();
    int nsamp = E2 / 2; if (nsamp > 2048) nsamp = 2048;
    for (int i = threadIdx.x; i < nsamp; i += blockDim.x)
        if (p[2 * i + 1] != 0u) atomicOr(&any, 1);
    __syncthreads();
    if (threadIdx.x == 0) g_is64 = any ? 0 : 1;
}

__device__ __forceinline__ int edge_val(const void* ei, size_t idx) {
    return g_is64 ? (int)((const long long*)ei)[idx] : ((const int*)ei)[idx];
}

// ---------------- degree / CSR ---------------------------------------------------
__global__ void count_deg(const void* __restrict__ ei, int E) {
    int e = blockIdx.x * blockDim.x + threadIdx.x;
    if (e >= E) return;
    int d = edge_val(ei, (size_t)E + e);
    atomicAdd(&g_deg[d], 1);
}
__global__ void scan1(int n) {
    __shared__ int sh[512];
    int i = blockIdx.x * 512 + threadIdx.x;
    int v = (i < n) ? g_deg[i] : 0;
    if (i < n) g_dis[i] = rsqrtf((float)(v + 1));
    sh[threadIdx.x] = v;
    __syncthreads();
    for (int off = 256; off > 0; off >>= 1) {
        if (threadIdx.x < off) sh[threadIdx.x] += sh[threadIdx.x + off];
        __syncthreads();
    }
    if (threadIdx.x == 0) g_bsum[blockIdx.x] = sh[0];
}
__global__ void scan2(int nb) {
    __shared__ int sh[1024];
    int tid = threadIdx.x;
    int v = (tid < nb) ? g_bsum[tid] : 0;
    sh[tid] = v;
    __syncthreads();
    for (int off = 1; off < 1024; off <<= 1) {
        int t = (tid >= off) ? sh[tid - off] : 0;
        __syncthreads();
        sh[tid] += t;
        __syncthreads();
    }
    if (tid < nb) g_bsum[tid] = sh[tid] - v;
}
__global__ void scan3(int n) {
    __shared__ int sh[512];
    int tid = threadIdx.x;
    int i = blockIdx.x * 512 + tid;
    int v = (i < n) ? g_deg[i] : 0;
    sh[tid] = v;
    __syncthreads();
    for (int off = 1; off < 512; off <<= 1) {
        int t = (tid >= off) ? sh[tid - off] : 0;
        __syncthreads();
        sh[tid] += t;
        __syncthreads();
    }
    if (i < n) {
        int rs = g_bsum[blockIdx.x] + sh[tid] - v;
        g_rowstart[i] = rs;
        g_cursor[i]   = rs;
    }
}
__global__ void fill_csr(const void* __restrict__ ei, int E) {
    int e = blockIdx.x * blockDim.x + threadIdx.x;
    if (e >= E) return;
    int s = edge_val(ei, e);
    int d = edge_val(ei, (size_t)E + e);
    int pos = atomicAdd(&g_cursor[d], 1);
    g_csr[pos] = s;
}

// ---------------- aggregation: warp per node, fp16 gather-sum --------------------
__device__ __forceinline__ float4 h4f(uint2 v) {
    const float2 f0 = __half22float2(*(const __half2*)&v.x);
    const float2 f1 = __half22float2(*(const __half2*)&v.y);
    return make_float4(f0.x, f0.y, f1.x, f1.y);
}
__global__ void aggregate(const float* __restrict__ b_gcn, int n) {
    int gw   = (blockIdx.x * blockDim.x + threadIdx.x) >> 5;
    int lane = threadIdx.x & 31;
    if (gw >= n) return;
    const int node = gw;
    const uint2* __restrict__ xg2 = (const uint2*)g_xgh;

    const float4 selfv = h4f(xg2[(size_t)node * 32 + lane]);
    const float  dn    = g_dis[node];
    const int    s0    = g_rowstart[node];
    const int    cnt   = g_deg[node];

    float4 acc = make_float4(0.f, 0.f, 0.f, 0.f);
    int e = s0, eend = s0 + cnt;
    for (; e + 1 < eend; e += 2) {
        const int s1 = g_csr[e], s2 = g_csr[e + 1];
        const float w1 = g_dis[s1], w2 = g_dis[s2];
        const float4 v1 = h4f(xg2[(size_t)s1 * 32 + lane]);
        const float4 v2 = h4f(xg2[(size_t)s2 * 32 + lane]);
        acc.x += v1.x * w1 + v2.x * w2;
        acc.y += v1.y * w1 + v2.y * w2;
        acc.z += v1.z * w1 + v2.z * w2;
        acc.w += v1.w * w1 + v2.w * w2;
    }
    if (e < eend) {
        const int s1 = g_csr[e];
        const float w1 = g_dis[s1];
        const float4 v1 = h4f(xg2[(size_t)s1 * 32 + lane]);
        acc.x += v1.x * w1; acc.y += v1.y * w1;
        acc.z += v1.z * w1; acc.w += v1.w * w1;
    }
    const float sw = dn * dn;
    const float4 b = ((const float4*)b_gcn)[lane];
    float4 o;
    o.x = fmaxf(acc.x * dn + selfv.x * sw + b.x, 0.f);
    o.y = fmaxf(acc.y * dn + selfv.y * sw + b.y, 0.f);
    o.z = fmaxf(acc.z * dn + selfv.z * sw + b.z, 0.f);
    o.w = fmaxf(acc.w * dn + selfv.w * sw + b.w, 0.f);
    // write diffused fp16 at k-permuted word positions
    const __half2 h0 = __floats2half2_rn(o.x, o.y);
    const __half2 h1 = __floats2half2_rn(o.z, o.w);
    uint32_t* drow = g_diffh + (size_t)node * 64;
    drow[permw(2 * lane)]     = *(const uint32_t*)&h0;
    drow[permw(2 * lane + 1)] = *(const uint32_t*)&h1;
}

// ---------------- launcher --------------------------------------------------------
extern "C" void kernel_launch(void* const* d_in, const int* in_sizes, int n_in,
                              void* d_out, int out_size)
{
    const float* base   = (const float*)d_in[0];
    const float* ev     = (const float*)d_in[1];
    const void*  ei     = d_in[2];
    const float* W_proj = (const float*)d_in[3];
    const float* b_proj = (const float*)d_in[4];
    const float* W_gcn  = (const float*)d_in[5];
    const float* b_gcn  = (const float*)d_in[6];
    const float* W_gate = (const float*)d_in[7];
    const float* b_gate = (const float*)d_in[8];
    const float* W_fuse = (const float*)d_in[9];
    const float* b_fuse = (const float*)d_in[10];

    const int N = in_sizes[0] / HID;
    const int E = in_sizes[2] / 2;

    uint32_t *p_xgh, *p_diffh, *p_evh, *p_baseh;
    __half *p_wtp, *p_wtg, *p_wtga, *p_wtf;
    int *p_deg;
    cudaGetSymbolAddress((void**)&p_xgh,   g_xgh);
    cudaGetSymbolAddress((void**)&p_diffh, g_diffh);
    cudaGetSymbolAddress((void**)&p_evh,   g_evh);
    cudaGetSymbolAddress((void**)&p_baseh, g_baseh);
    cudaGetSymbolAddress((void**)&p_wtp,   g_wt_proj);
    cudaGetSymbolAddress((void**)&p_wtg,   g_wt_gcn);
    cudaGetSymbolAddress((void**)&p_wtga,  g_wt_gate);
    cudaGetSymbolAddress((void**)&p_wtf,   g_wt_fuse);
    cudaGetSymbolAddress((void**)&p_deg,   g_deg);

    cudaFuncSetAttribute(k_proj_gcn,  cudaFuncAttributeMaxDynamicSharedMemorySize, PG_SMEM_W * 4);
    cudaFuncSetAttribute(k_gate_fuse, cudaFuncAttributeMaxDynamicSharedMemorySize, GF_SMEM_W * 4);

    const int gT = (N + 127) / 128;
    const int gE = (E + 255) / 256;
    const int nb = (N + 511) / 512;

    // fork side stream for CSR chain
    cudaStream_t side;
    cudaEvent_t evFork, evJoin;
    cudaStreamCreateWithFlags(&side, cudaStreamNonBlocking);
    cudaEventCreateWithFlags(&evFork, cudaEventDisableTiming);
    cudaEventCreateWithFlags(&evJoin, cudaEventDisableTiming);

    cudaEventRecord(evFork, 0);
    cudaStreamWaitEvent(side, evFork, 0);

    // --- side: CSR build
    detect_idx<<<1, 256, 0, side>>>((const unsigned int*)ei, 2 * E);
    cudaMemsetAsync(p_deg, 0, (size_t)N * sizeof(int), side);
    count_deg<<<gE, 256, 0, side>>>(ei, E);
    scan1<<<nb, 512, 0, side>>>(N);
    scan2<<<1, 1024, 0, side>>>(nb);
    scan3<<<nb, 512, 0, side>>>(N);
    fill_csr<<<gE, 256, 0, side>>>(ei, E);
    cudaEventRecord(evJoin, side);

    // --- main: prep + fused proj/gcn + base convert (overlaps CSR)
    wprep<<<88, 256>>>(W_proj, W_gcn, W_gate, W_fuse, p_wtp, p_wtg, p_wtga, p_wtf);
    cvt_half<32><<<(N * 32 + 255) / 256, 256>>>((const float2*)ev, p_evh, N * 32);
    k_proj_gcn<<<gT, 256, PG_SMEM_W * 4>>>(p_evh, p_wtp, b_proj, p_wtg, p_xgh, N);
    cvt_half<64><<<(N * 64 + 255) / 256, 256>>>((const float2*)base, p_baseh, N * 64);

    // join: aggregate needs xg (main) + CSR (side)
    cudaStreamWaitEvent(0, evJoin, 0);
    aggregate<<<(N * 32 + 255) / 256, 256>>>(b_gcn, N);

    k_gate_fuse<<<gT, 256, GF_SMEM_W * 4>>>(p_baseh, p_diffh, p_wtga, b_gate,
                                            p_wtf, b_fuse, (float*)d_out, N);
}